// round 11
// baseline (speedup 1.0000x reference)
#include <cuda_runtime.h>
#include <math.h>

#define NN 50000
#define EE 800000
#define NF  512
#define NH  128
#define NC  16
#define EPSF 1e-9f

// ---------------- scratch (static device allocations) ----------------
__device__ float g_h1[NN * NH];
__device__ float g_rst1[NN * NH];
__device__ float g_hlatp[NN * NC];
__device__ float g_hlatp2[NN * NC];
__device__ float g_h2[NN * NC];
__device__ float g_rst2[NN * NC];
__device__ float g_el1[NN], g_er1[NN];
__device__ float g_el2[NN], g_er2[NN];
__device__ float g_indeg[NN];
__device__ float g_outw1[NN], g_inw1[NN], g_outw2[NN], g_inw2[NN];
__device__ float g_ew1[EE], g_ew2[EE];
__device__ float g_lp;
__device__ float g_scal[8];

// ---------------- helpers ----------------
__device__ __forceinline__ float eluf(float x) { return x > 0.f ? x : expm1f(x); }
__device__ __forceinline__ float leakyf(float x) { return x > 0.f ? x : 0.2f * x; }

__device__ __forceinline__ void red_add_v4(float* addr, float4 v) {
    asm volatile("red.global.add.v4.f32 [%0], {%1,%2,%3,%4};"
                 :: "l"(addr), "f"(v.x), "f"(v.y), "f"(v.z), "f"(v.w) : "memory");
}

__device__ __forceinline__ unsigned smem_u32(const void* p) {
    unsigned r;
    asm("{ .reg .u64 t; cvta.to.shared.u64 t, %1; cvt.u32.u64 %0, t; }"
        : "=r"(r) : "l"(p));
    return r;
}

__device__ __forceinline__ unsigned pack_bf16(float a, float b) {
    unsigned r;
    asm("cvt.rn.bf16x2.f32 %0, %1, %2;" : "=r"(r) : "f"(b), "f"(a));
    return r;
}
__device__ __forceinline__ float bf16lo_f(unsigned p) { return __uint_as_float(p << 16); }
__device__ __forceinline__ float bf16hi_f(unsigned p) { return __uint_as_float(p & 0xffff0000u); }

__device__ __forceinline__ void ldsm_x4(unsigned& r0, unsigned& r1, unsigned& r2, unsigned& r3,
                                        unsigned addr) {
    asm volatile("ldmatrix.sync.aligned.m8n8.x4.shared.b16 {%0,%1,%2,%3}, [%4];"
                 : "=r"(r0), "=r"(r1), "=r"(r2), "=r"(r3) : "r"(addr));
}
__device__ __forceinline__ void ldsm_x4_t(unsigned& r0, unsigned& r1, unsigned& r2, unsigned& r3,
                                          unsigned addr) {
    asm volatile("ldmatrix.sync.aligned.m8n8.x4.trans.shared.b16 {%0,%1,%2,%3}, [%4];"
                 : "=r"(r0), "=r"(r1), "=r"(r2), "=r"(r3) : "r"(addr));
}
__device__ __forceinline__ void mma_bf16(float* c, const unsigned* a, const unsigned* b) {
    asm volatile(
        "mma.sync.aligned.m16n8k16.row.col.f32.bf16.bf16.f32 "
        "{%0,%1,%2,%3}, {%4,%5,%6,%7}, {%8,%9}, {%0,%1,%2,%3};"
        : "+f"(c[0]), "+f"(c[1]), "+f"(c[2]), "+f"(c[3])
        : "r"(a[0]), "r"(a[1]), "r"(a[2]), "r"(a[3]), "r"(b[0]), "r"(b[1]));
}

__device__ __forceinline__ void split_pack(float v0, float v1, unsigned& hi, unsigned& lo) {
    hi = pack_bf16(v0, v1);
    float h0 = bf16lo_f(hi);
    float h1 = bf16hi_f(hi);
    lo = pack_bf16(v0 - h0, v1 - h1);
}

// ---------------- zero scratch ----------------
__global__ void k_zero() {
    int i = blockIdx.x * blockDim.x + threadIdx.x;
    int st = gridDim.x * blockDim.x;
    for (int j = i; j < NN * NH; j += st) g_rst1[j] = 0.f;
    for (int j = i; j < NN * NC; j += st) g_rst2[j] = 0.f;
    for (int j = i; j < NN; j += st) {
        g_indeg[j] = 0.f;
        g_outw1[j] = 0.f; g_inw1[j] = 0.f;
        g_outw2[j] = 0.f; g_inw2[j] = 0.f;
        g_el1[j] = 0.f; g_er1[j] = 0.f;
    }
    if (i == 0) g_lp = 0.f;
}

// ---------------- derived scalars ----------------
__global__ void k_scalars(const float* beta1, const float* aw1, const float* theta1,
                          const float* beta2, const float* aw2, const float* theta2) {
    if (threadIdx.x == 0) {
        g_scal[0] = 2.f / (expf(-beta1[0]) + 1.f);
        float m1 = fmaxf(aw1[0], aw1[1]);
        float a0 = expf(aw1[0] - m1), a1 = expf(aw1[1] - m1);
        g_scal[1] = a0 / (a0 + a1);
        g_scal[2] = a1 / (a0 + a1);
        g_scal[3] = EPSF / (expf(-theta1[0]) + 1.f);

        g_scal[4] = 2.f / (expf(-beta2[0]) + 1.f);
        float m2 = fmaxf(aw2[0], aw2[1]);
        float b0 = expf(aw2[0] - m2), b1 = expf(aw2[1] - m2);
        g_scal[5] = b0 / (b0 + b1);
        g_scal[6] = b1 / (b0 + b1);
        g_scal[7] = EPSF / (expf(-theta2[0]) + 1.f);
    }
}

// ---------------- hlatp / hlatp2 ----------------
__global__ void k_latp(const float* __restrict__ latp,
                       const float* __restrict__ sl_w, const float* __restrict__ sl_b,
                       const float* __restrict__ slo_w, const float* __restrict__ slo_b) {
    __shared__ float W1[NC * NC], W2[NC * NC], B1[NC], B2[NC];
    int t = threadIdx.x;
    if (t < NC * NC) { W1[t] = sl_w[t]; W2[t] = slo_w[t]; }
    if (t < NC) { B1[t] = sl_b[t]; B2[t] = slo_b[t]; }
    __syncthreads();
    int n = blockIdx.x * blockDim.x + t;
    if (n >= NN) return;

    float in[NC], t1[NC];
#pragma unroll
    for (int j = 0; j < NC; j++) in[j] = latp[n * NC + j];
#pragma unroll
    for (int c = 0; c < NC; c++) {
        float acc = B1[c];
#pragma unroll
        for (int j = 0; j < NC; j++) acc += in[j] * W1[j * NC + c];
        t1[c] = eluf(acc);
        g_hlatp[n * NC + c] = t1[c];
    }
#pragma unroll
    for (int c = 0; c < NC; c++) {
        float acc = B2[c];
#pragma unroll
        for (int j = 0; j < NC; j++) acc += t1[j] * W2[j * NC + c];
        g_hlatp2[n * NC + c] = eluf(acc);
    }
}

// ---------------- tensor GEMM: h1 = x @ fc1_w, bf16 split, 512 threads, single buffer ----------------
#define BM 128
#define BN 128
#define BK 32
#define SA 40
#define SBW 136

// A staging: ar = tid>>2 (0..127), quad = (tid&3) + 4q
// B staging: br = tid>>4 (0..31),  quad = (tid&15) + 16q
#define LOAD_REGS(KT) do {                                                        \
    int kbase = (KT) * BK;                                                        \
    _Pragma("unroll")                                                             \
    for (int q = 0; q < 2; q++) {                                                 \
        int ac = (((tid & 3) + 4 * q) << 2);                                      \
        int gm = m0 + ar;                                                         \
        if (gm < NN) pa[q] = *(const float4*)(x + (size_t)gm * NF + kbase + ac);  \
        else pa[q] = make_float4(0.f, 0.f, 0.f, 0.f);                             \
        int bc = (((tid & 15) + 16 * q) << 2);                                    \
        pb[q] = *(const float4*)(w + (size_t)(kbase + br) * BN + bc);             \
    }                                                                             \
} while (0)

#define STORE_STAGE() do {                                                        \
    _Pragma("unroll")                                                             \
    for (int q = 0; q < 2; q++) {                                                 \
        unsigned hi, lo;                                                          \
        int ac = (((tid & 3) + 4 * q) << 2);                                      \
        int ai = (ar * SA + ac) >> 1;                                             \
        split_pack(pa[q].x, pa[q].y, hi, lo);                                     \
        sAhi[ai] = hi; sAlo[ai] = lo;                                             \
        split_pack(pa[q].z, pa[q].w, hi, lo);                                     \
        sAhi[ai + 1] = hi; sAlo[ai + 1] = lo;                                     \
        int bc = (((tid & 15) + 16 * q) << 2);                                    \
        int bi = (br * SBW + bc) >> 1;                                            \
        split_pack(pb[q].x, pb[q].y, hi, lo);                                     \
        sBhi[bi] = hi; sBlo[bi] = lo;                                             \
        split_pack(pb[q].z, pb[q].w, hi, lo);                                     \
        sBhi[bi + 1] = hi; sBlo[bi + 1] = lo;                                     \
    }                                                                             \
} while (0)

__global__ void __launch_bounds__(512, 1)
k_gemm1(const float* __restrict__ x, const float* __restrict__ w,
        const float* __restrict__ wu, const float* __restrict__ wv) {
    __shared__ unsigned sAhi[BM * SA / 2];
    __shared__ unsigned sAlo[BM * SA / 2];
    __shared__ unsigned sBhi[BK * SBW / 2];
    __shared__ unsigned sBlo[BK * SBW / 2];

    const int tid = threadIdx.x;
    const int lane = tid & 31;
    const int wp = tid >> 5;              // 0..15
    const int wm = (wp & 3) * 32;         // 4 warps along M
    const int wn = (wp >> 2) * 32;        // 4 warps along N
    const int m0 = blockIdx.x * BM;

    const unsigned aHiB = smem_u32(sAhi);
    const unsigned aLoB = smem_u32(sAlo);
    const unsigned bHiB = smem_u32(sBhi);
    const unsigned bLoB = smem_u32(sBlo);

    const int i8 = lane >> 3;
    const int w8 = lane & 7;

    const int ar = tid >> 2;              // A staging row 0..127
    const int br = tid >> 4;              // B staging row 0..31

    float acc[2][4][4];
#pragma unroll
    for (int i = 0; i < 2; i++)
#pragma unroll
        for (int j = 0; j < 4; j++)
#pragma unroll
            for (int k = 0; k < 4; k++) acc[i][j][k] = 0.f;

    float4 pa[2], pb[2];
    const int NT = NF / BK;   // 16

    LOAD_REGS(0);
    STORE_STAGE();
    __syncthreads();

    for (int kt = 0; kt < NT; kt++) {
        if (kt + 1 < NT) LOAD_REGS(kt + 1);

#pragma unroll
        for (int ks = 0; ks < 2; ks++) {
            int k0 = ks * 16;
            unsigned bh[4][2], bl[4][2];
            int brow = k0 + ((i8 & 1) << 3) + w8;
#pragma unroll
            for (int p = 0; p < 2; p++) {
                int bcol = wn + p * 16 + ((i8 >> 1) << 3);
                unsigned off = (unsigned)(brow * SBW + bcol) * 2u;
                ldsm_x4_t(bh[2 * p][0], bh[2 * p][1], bh[2 * p + 1][0], bh[2 * p + 1][1],
                          bHiB + off);
                ldsm_x4_t(bl[2 * p][0], bl[2 * p][1], bl[2 * p + 1][0], bl[2 * p + 1][1],
                          bLoB + off);
            }
#pragma unroll
            for (int mt = 0; mt < 2; mt++) {
                int arow = wm + mt * 16 + ((i8 & 1) << 3) + w8;
                int acol = k0 + ((i8 >> 1) << 3);
                unsigned off = (unsigned)(arow * SA + acol) * 2u;
                unsigned ah[4], al[4];
                ldsm_x4(ah[0], ah[1], ah[2], ah[3], aHiB + off);
                ldsm_x4(al[0], al[1], al[2], al[3], aLoB + off);
#pragma unroll
                for (int nt = 0; nt < 4; nt++) {
                    mma_bf16(acc[mt][nt], ah, bh[nt]);
                    mma_bf16(acc[mt][nt], ah, bl[nt]);
                    mma_bf16(acc[mt][nt], al, bh[nt]);
                }
            }
        }

        if (kt + 1 < NT) {
            __syncthreads();
            STORE_STAGE();
            __syncthreads();
        }
    }

    // epilogue: store h1 + fused el1/er1 partials
#pragma unroll
    for (int mt = 0; mt < 2; mt++) {
        int r0 = m0 + wm + mt * 16 + (lane >> 2);
        int r1 = r0 + 8;
        float pu0 = 0.f, pv0 = 0.f, pu1 = 0.f, pv1 = 0.f;
#pragma unroll
        for (int nt = 0; nt < 4; nt++) {
            int col = wn + nt * 8 + ((lane & 3) << 1);
            float u0 = wu[col], u1 = wu[col + 1];
            float v0 = wv[col], v1 = wv[col + 1];
            float l00 = leakyf(acc[mt][nt][0]), l01 = leakyf(acc[mt][nt][1]);
            float l10 = leakyf(acc[mt][nt][2]), l11 = leakyf(acc[mt][nt][3]);
            pu0 += l00 * u0 + l01 * u1;
            pv0 += l00 * v0 + l01 * v1;
            pu1 += l10 * u0 + l11 * u1;
            pv1 += l10 * v0 + l11 * v1;
            if (r0 < NN)
                *(float2*)&g_h1[(size_t)r0 * NH + col] = make_float2(acc[mt][nt][0], acc[mt][nt][1]);
            if (r1 < NN)
                *(float2*)&g_h1[(size_t)r1 * NH + col] = make_float2(acc[mt][nt][2], acc[mt][nt][3]);
        }
        pu0 += __shfl_down_sync(0xffffffffu, pu0, 2, 4);
        pu0 += __shfl_down_sync(0xffffffffu, pu0, 1, 4);
        pv0 += __shfl_down_sync(0xffffffffu, pv0, 2, 4);
        pv0 += __shfl_down_sync(0xffffffffu, pv0, 1, 4);
        pu1 += __shfl_down_sync(0xffffffffu, pu1, 2, 4);
        pu1 += __shfl_down_sync(0xffffffffu, pu1, 1, 4);
        pv1 += __shfl_down_sync(0xffffffffu, pv1, 2, 4);
        pv1 += __shfl_down_sync(0xffffffffu, pv1, 1, 4);
        if ((lane & 3) == 0) {
            if (r0 < NN) { atomicAdd(&g_el1[r0], pu0); atomicAdd(&g_er1[r0], pv0); }
            if (r1 < NN) { atomicAdd(&g_el1[r1], pu1); atomicAdd(&g_er1[r1], pv1); }
        }
    }
}

// ---------------- layer1 edge pass A: 16-lane edge groups, 2 edges/warp ----------------
__global__ void k_edgeA1(const int* __restrict__ src, const int* __restrict__ dst,
                         const float* __restrict__ ws1) {
    int gt = blockIdx.x * blockDim.x + threadIdx.x;
    int l = threadIdx.x & 15;
    int grp = gt >> 4;
    int ngr = (gridDim.x * blockDim.x) >> 4;
    float wsv = ws1[l];
    float bw = g_scal[0];
    float bw0 = bw * g_scal[1], bw1 = bw * g_scal[2];

    for (int e = grp; e < EE; e += ngr) {
        int s = src[e], d = dst[e];
        const float4* as = (const float4*)(g_h1 + (size_t)s * NH);
        const float4* ad = (const float4*)(g_h1 + (size_t)d * NH);
        float4 a0 = as[2 * l], a1 = as[2 * l + 1];
        float4 b0 = ad[2 * l], b1 = ad[2 * l + 1];
        float d0 = a0.x - b0.x, d1 = a0.y - b0.y, d2 = a0.z - b0.z, d3 = a0.w - b0.w;
        float d4 = a1.x - b1.x, d5 = a1.y - b1.y, d6 = a1.z - b1.z, d7 = a1.w - b1.w;
        float sdf = d0 * d0 + d1 * d1 + d2 * d2 + d3 * d3
                  + d4 * d4 + d5 * d5 + d6 * d6 + d7 * d7;
        float ps = g_hlatp[(size_t)s * NC + l];
        float pd = g_hlatp[(size_t)d * NC + l];
        float df = ps - pd;
        float sds = df * df;
        float st = ps * wsv * pd;
#pragma unroll
        for (int off = 8; off; off >>= 1) {
            sdf += __shfl_down_sync(0xffffffffu, sdf, off, 16);
            sds += __shfl_down_sync(0xffffffffu, sds, off, 16);
            st  += __shfl_down_sync(0xffffffffu, st, off, 16);
        }
        if (l == 0) {
            float ee = g_el1[s] + g_er1[d] + st;
            float ew = expf(ee - bw0 * sdf - bw1 * sds) + EPSF;
            g_ew1[e] = ew;
            atomicAdd(&g_outw1[s], ew);
            atomicAdd(&g_inw1[d], ew);
            atomicAdd(&g_indeg[d], 1.0f);
        }
    }
}

// ---------------- layer1 edge pass B (coef inlined, uniform loads) ----------------
__global__ void k_edgeB1(const int* __restrict__ src, const int* __restrict__ dst) {
    int gt = blockIdx.x * blockDim.x + threadIdx.x;
    int lane = threadIdx.x & 31;
    int gw = gt >> 5;
    int nw = (gridDim.x * blockDim.x) >> 5;
    for (int e = gw; e < EE; e += nw) {
        int s = src[e], d = dst[e];
        float a = rsqrtf(g_outw1[s]) * rsqrtf(g_inw1[d]) * g_ew1[e];
        float4 h = ((const float4*)(g_h1 + (size_t)s * NH))[lane];
        h.x *= a; h.y *= a; h.z *= a; h.w *= a;
        red_add_v4(&g_rst1[(size_t)d * NH + (lane << 2)], h);
    }
}

// ---------------- fused: h = elu(rst1 + h1*perm) ; h2 = h @ fc2_w ; el2/er2 ----------------
__global__ void k_fc2(const float* __restrict__ w, const float* __restrict__ wu,
                      const float* __restrict__ wv) {
    __shared__ float Ws[NH * NC];
    __shared__ float Hrow[8][NH];
    int t = threadIdx.x;
    for (int j = t; j < NH * NC; j += blockDim.x) Ws[j] = w[j];
    __syncthreads();

    int lane = t & 31;
    int wid = t >> 5;
    int c = lane & 15;
    int half = lane >> 4;
    int gw = (blockIdx.x * blockDim.x + t) >> 5;
    int nw = (gridDim.x * blockDim.x) >> 5;
    float wuc = wu[c], wvc = wv[c];
    float pc = g_scal[3];

    for (int n = gw; n < NN; n += nw) {
        float perm = pc / (g_indeg[n] + EPSF);
        float4 r = ((const float4*)(g_rst1 + (size_t)n * NH))[lane];
        float4 hh = ((const float4*)(g_h1 + (size_t)n * NH))[lane];
        float4 o;
        o.x = eluf(r.x + hh.x * perm);
        o.y = eluf(r.y + hh.y * perm);
        o.z = eluf(r.z + hh.z * perm);
        o.w = eluf(r.w + hh.w * perm);
        *(float4*)&Hrow[wid][lane << 2] = o;
        __syncwarp();

        float acc = 0.f;
        int kb = half * 64;
#pragma unroll
        for (int k = 0; k < 64; k++) acc += Hrow[wid][kb + k] * Ws[(kb + k) * NC + c];
        acc += __shfl_xor_sync(0xffffffffu, acc, 16);
        if (half == 0) g_h2[(size_t)n * NC + c] = acc;
        float lr = leakyf(acc);
        float pu = lr * wuc, pv = lr * wvc;
#pragma unroll
        for (int off = 8; off; off >>= 1) {
            pu += __shfl_down_sync(0xffffffffu, pu, off, 16);
            pv += __shfl_down_sync(0xffffffffu, pv, off, 16);
        }
        if (lane == 0) { g_el2[n] = pu; g_er2[n] = pv; }
        __syncwarp();
    }
}

// ---------------- layer2 edge pass A ----------------
__global__ void k_edgeA2(const int* __restrict__ src, const int* __restrict__ dst,
                         const float* __restrict__ ws2, const float* __restrict__ wts) {
    __shared__ float redbuf[256];
    int t = threadIdx.x;
    int c = t & 15;
    int grp = (blockIdx.x * blockDim.x + t) >> 4;
    int ngr = (gridDim.x * blockDim.x) >> 4;
    float wsv = ws2[c];
    float bw = g_scal[4], w0 = g_scal[5], w1 = g_scal[6];
    float lpacc = 0.f;

    for (int e = grp; e < EE; e += ngr) {
        int s = src[e], d = dst[e];
        float hs = g_h2[(size_t)s * NC + c], hd = g_h2[(size_t)d * NC + c];
        float ps = g_hlatp2[(size_t)s * NC + c], pd = g_hlatp2[(size_t)d * NC + c];
        float df = hs - hd;
        float sdf = df * df;
        float dp = ps - pd;
        float sds = dp * dp;
        float prod = ps * pd;
        float st = prod * wsv;
#pragma unroll
        for (int off = 8; off; off >>= 1) {
            sdf  += __shfl_down_sync(0xffffffffu, sdf, off, 16);
            sds  += __shfl_down_sync(0xffffffffu, sds, off, 16);
            st   += __shfl_down_sync(0xffffffffu, st, off, 16);
            prod += __shfl_down_sync(0xffffffffu, prod, off, 16);
        }
        if (c == 0) {
            float ee = g_el2[s] + g_er2[d] + st;
            float ew = expf(ee - bw * (w0 * sdf + w1 * sds)) + EPSF;
            g_ew2[e] = ew;
            atomicAdd(&g_outw2[s], ew);
            atomicAdd(&g_inw2[d], ew);
            lpacc += wts[e] * prod;
        }
    }
    redbuf[t] = lpacc;
    __syncthreads();
    for (int s2 = 128; s2; s2 >>= 1) {
        if (t < s2) redbuf[t] += redbuf[t + s2];
        __syncthreads();
    }
    if (t == 0) atomicAdd(&g_lp, redbuf[0]);
}

// ---------------- layer2 edge pass B (coef inlined) ----------------
__global__ void k_edgeB2(const int* __restrict__ src, const int* __restrict__ dst) {
    int gt = blockIdx.x * blockDim.x + threadIdx.x;
    int sub = gt & 3;
    int grp = gt >> 2;
    int ngr = (gridDim.x * blockDim.x) >> 2;
    for (int e = grp; e < EE; e += ngr) {
        int s = src[e], d = dst[e];
        float a = rsqrtf(g_outw2[s]) * rsqrtf(g_inw2[d]) * g_ew2[e];
        float4 h = ((const float4*)(g_h2 + (size_t)s * NC))[sub];
        h.x *= a; h.y *= a; h.z *= a; h.w *= a;
        red_add_v4(&g_rst2[(size_t)d * NC + (sub << 2)], h);
    }
}

// ---------------- final ----------------
__global__ void k_final(float* __restrict__ out, int out_size) {
    int t = threadIdx.x;
    int c = t & 15;
    int grp = (blockIdx.x * blockDim.x + t) >> 4;
    int ngr = (gridDim.x * blockDim.x) >> 4;
    float pc = g_scal[7];

    for (int n = grp; n < NN; n += ngr) {
        float perm = pc / (g_indeg[n] + EPSF);
        float v = g_rst2[(size_t)n * NC + c] + g_h2[(size_t)n * NC + c] * perm;
        float xv = eluf(v);
        float m = xv;
#pragma unroll
        for (int off = 8; off; off >>= 1)
            m = fmaxf(m, __shfl_xor_sync(0xffffffffu, m, off, 16));
        float ex = expf(xv - m);
        float ssum = ex;
#pragma unroll
        for (int off = 8; off; off >>= 1)
            ssum += __shfl_xor_sync(0xffffffffu, ssum, off, 16);
        out[(size_t)n * NC + c] = xv - m - logf(ssum);
    }
    if (blockIdx.x == 0 && t == 0 && out_size > NN * NC)
        out[NN * NC] = g_lp;
}

// ---------------- launch ----------------
extern "C" void kernel_launch(void* const* d_in, const int* in_sizes, int n_in,
                              void* d_out, int out_size) {
    const int*   src    = (const int*)d_in[0];
    const int*   dst    = (const int*)d_in[1];
    const float* x      = (const float*)d_in[2];
    const float* wts    = (const float*)d_in[3];
    const float* latp   = (const float*)d_in[4];
    const float* sl_w   = (const float*)d_in[5];
    const float* sl_b   = (const float*)d_in[6];
    const float* slo_w  = (const float*)d_in[7];
    const float* slo_b  = (const float*)d_in[8];
    const float* fc1_w  = (const float*)d_in[9];
    const float* w_u1   = (const float*)d_in[10];
    const float* w_v1   = (const float*)d_in[11];
    const float* w_s1   = (const float*)d_in[12];
    const float* beta1  = (const float*)d_in[13];
    const float* aw1    = (const float*)d_in[14];
    const float* theta1 = (const float*)d_in[15];
    const float* fc2_w  = (const float*)d_in[16];
    const float* w_u2   = (const float*)d_in[17];
    const float* w_v2   = (const float*)d_in[18];
    const float* w_s2   = (const float*)d_in[19];
    const float* beta2  = (const float*)d_in[20];
    const float* aw2    = (const float*)d_in[21];
    const float* theta2 = (const float*)d_in[22];
    float* out = (float*)d_out;

    k_zero<<<1024, 256>>>();
    k_scalars<<<1, 32>>>(beta1, aw1, theta1, beta2, aw2, theta2);
    k_latp<<<(NN + 255) / 256, 256>>>(latp, sl_w, sl_b, slo_w, slo_b);
    k_gemm1<<<(NN + BM - 1) / BM, 512>>>(x, fc1_w, w_u1, w_v1);
    k_edgeA1<<<4096, 256>>>(src, dst, w_s1);
    k_edgeB1<<<4096, 256>>>(src, dst);
    k_fc2<<<2048, 256>>>(fc2_w, w_u2, w_v2);
    k_edgeA2<<<2048, 256>>>(src, dst, w_s2, wts);
    k_edgeB2<<<2048, 256>>>(src, dst);
    k_final<<<2048, 256>>>(out, out_size);
}

// round 12
// speedup vs baseline: 1.0840x; 1.0840x over previous
#include <cuda_runtime.h>
#include <math.h>

#define NN 50000
#define EE 800000
#define NF  512
#define NH  128
#define NC  16
#define EPSF 1e-9f

// ---------------- scratch (static device allocations) ----------------
__device__ float g_h1[NN * NH];
__device__ float g_h[NN * NH];
__device__ float g_hlatp[NN * NC];
__device__ float g_hlatp2[NN * NC];
__device__ float g_h2[NN * NC];
__device__ float g_rst2[NN * NC];
__device__ float g_el1[NN], g_er1[NN];
__device__ float g_el2[NN], g_er2[NN];
__device__ float g_indeg[NN];
__device__ float g_outw1[NN], g_inw1[NN], g_outw2[NN], g_inw2[NN];
__device__ float g_ew1[EE], g_ew2[EE];
__device__ float g_lp;
__device__ float g_scal[8];
// CSR
__device__ int g_exc[NN];
__device__ int g_bsum[64];
__device__ int g_bexc[64];
__device__ int g_start[NN];
__device__ int g_cursor[NN];
__device__ int g_csrc[EE];
__device__ float g_cw[EE];

// ---------------- helpers ----------------
__device__ __forceinline__ float eluf(float x) { return x > 0.f ? x : expm1f(x); }
__device__ __forceinline__ float leakyf(float x) { return x > 0.f ? x : 0.2f * x; }

__device__ __forceinline__ void red_add_v4(float* addr, float4 v) {
    asm volatile("red.global.add.v4.f32 [%0], {%1,%2,%3,%4};"
                 :: "l"(addr), "f"(v.x), "f"(v.y), "f"(v.z), "f"(v.w) : "memory");
}

__device__ __forceinline__ unsigned smem_u32(const void* p) {
    unsigned r;
    asm("{ .reg .u64 t; cvta.to.shared.u64 t, %1; cvt.u32.u64 %0, t; }"
        : "=r"(r) : "l"(p));
    return r;
}

__device__ __forceinline__ unsigned pack_bf16(float a, float b) {
    unsigned r;
    asm("cvt.rn.bf16x2.f32 %0, %1, %2;" : "=r"(r) : "f"(b), "f"(a));
    return r;
}
__device__ __forceinline__ float bf16lo_f(unsigned p) { return __uint_as_float(p << 16); }
__device__ __forceinline__ float bf16hi_f(unsigned p) { return __uint_as_float(p & 0xffff0000u); }

__device__ __forceinline__ void ldsm_x4(unsigned& r0, unsigned& r1, unsigned& r2, unsigned& r3,
                                        unsigned addr) {
    asm volatile("ldmatrix.sync.aligned.m8n8.x4.shared.b16 {%0,%1,%2,%3}, [%4];"
                 : "=r"(r0), "=r"(r1), "=r"(r2), "=r"(r3) : "r"(addr));
}
__device__ __forceinline__ void ldsm_x4_t(unsigned& r0, unsigned& r1, unsigned& r2, unsigned& r3,
                                          unsigned addr) {
    asm volatile("ldmatrix.sync.aligned.m8n8.x4.trans.shared.b16 {%0,%1,%2,%3}, [%4];"
                 : "=r"(r0), "=r"(r1), "=r"(r2), "=r"(r3) : "r"(addr));
}
__device__ __forceinline__ void mma_bf16(float* c, const unsigned* a, const unsigned* b) {
    asm volatile(
        "mma.sync.aligned.m16n8k16.row.col.f32.bf16.bf16.f32 "
        "{%0,%1,%2,%3}, {%4,%5,%6,%7}, {%8,%9}, {%0,%1,%2,%3};"
        : "+f"(c[0]), "+f"(c[1]), "+f"(c[2]), "+f"(c[3])
        : "r"(a[0]), "r"(a[1]), "r"(a[2]), "r"(a[3]), "r"(b[0]), "r"(b[1]));
}

__device__ __forceinline__ void split_pack(float v0, float v1, unsigned& hi, unsigned& lo) {
    hi = pack_bf16(v0, v1);
    float h0 = bf16lo_f(hi);
    float h1 = bf16hi_f(hi);
    lo = pack_bf16(v0 - h0, v1 - h1);
}

// ---------------- zero scratch ----------------
__global__ void k_zero() {
    int i = blockIdx.x * blockDim.x + threadIdx.x;
    int st = gridDim.x * blockDim.x;
    for (int j = i; j < NN * NC; j += st) g_rst2[j] = 0.f;
    for (int j = i; j < NN; j += st) {
        g_indeg[j] = 0.f;
        g_outw1[j] = 0.f; g_inw1[j] = 0.f;
        g_outw2[j] = 0.f; g_inw2[j] = 0.f;
        g_el1[j] = 0.f; g_er1[j] = 0.f;
    }
    if (i == 0) g_lp = 0.f;
}

// ---------------- derived scalars ----------------
__global__ void k_scalars(const float* beta1, const float* aw1, const float* theta1,
                          const float* beta2, const float* aw2, const float* theta2) {
    if (threadIdx.x == 0) {
        g_scal[0] = 2.f / (expf(-beta1[0]) + 1.f);
        float m1 = fmaxf(aw1[0], aw1[1]);
        float a0 = expf(aw1[0] - m1), a1 = expf(aw1[1] - m1);
        g_scal[1] = a0 / (a0 + a1);
        g_scal[2] = a1 / (a0 + a1);
        g_scal[3] = EPSF / (expf(-theta1[0]) + 1.f);

        g_scal[4] = 2.f / (expf(-beta2[0]) + 1.f);
        float m2 = fmaxf(aw2[0], aw2[1]);
        float b0 = expf(aw2[0] - m2), b1 = expf(aw2[1] - m2);
        g_scal[5] = b0 / (b0 + b1);
        g_scal[6] = b1 / (b0 + b1);
        g_scal[7] = EPSF / (expf(-theta2[0]) + 1.f);
    }
}

// ---------------- hlatp / hlatp2 ----------------
__global__ void k_latp(const float* __restrict__ latp,
                       const float* __restrict__ sl_w, const float* __restrict__ sl_b,
                       const float* __restrict__ slo_w, const float* __restrict__ slo_b) {
    __shared__ float W1[NC * NC], W2[NC * NC], B1[NC], B2[NC];
    int t = threadIdx.x;
    if (t < NC * NC) { W1[t] = sl_w[t]; W2[t] = slo_w[t]; }
    if (t < NC) { B1[t] = sl_b[t]; B2[t] = slo_b[t]; }
    __syncthreads();
    int n = blockIdx.x * blockDim.x + t;
    if (n >= NN) return;

    float in[NC], t1[NC];
#pragma unroll
    for (int j = 0; j < NC; j++) in[j] = latp[n * NC + j];
#pragma unroll
    for (int c = 0; c < NC; c++) {
        float acc = B1[c];
#pragma unroll
        for (int j = 0; j < NC; j++) acc += in[j] * W1[j * NC + c];
        t1[c] = eluf(acc);
        g_hlatp[n * NC + c] = t1[c];
    }
#pragma unroll
    for (int c = 0; c < NC; c++) {
        float acc = B2[c];
#pragma unroll
        for (int j = 0; j < NC; j++) acc += t1[j] * W2[j * NC + c];
        g_hlatp2[n * NC + c] = eluf(acc);
    }
}

// ---------------- tensor GEMM: h1 = x @ fc1_w, bf16 split, double-buffered (R9) ----------------
#define BM 128
#define BN 128
#define BK 32
#define SA 40
#define SBW 136
#define ABY (BM * SA * 2)
#define BBY (BK * SBW * 2)

#define LOAD_REGS(KT) do {                                                        \
    int kbase = (KT) * BK;                                                        \
    _Pragma("unroll")                                                             \
    for (int q = 0; q < 4; q++) {                                                 \
        int gm = m0 + ar + 32 * q;                                                \
        if (gm < NN) pa[q] = *(const float4*)(x + (size_t)gm * NF + kbase + ac4); \
        else pa[q] = make_float4(0.f, 0.f, 0.f, 0.f);                             \
        int bc4 = ((tid & 7) + 8 * q) << 2;                                       \
        pb[q] = *(const float4*)(w + (size_t)(kbase + ar) * BN + bc4);            \
    }                                                                             \
} while (0)

#define STORE_STAGE(BUF) do {                                                     \
    _Pragma("unroll")                                                             \
    for (int q = 0; q < 4; q++) {                                                 \
        int r = ar + 32 * q;                                                      \
        unsigned hi, lo;                                                          \
        int ai = (r * SA + ac4) >> 1;                                             \
        split_pack(pa[q].x, pa[q].y, hi, lo);                                     \
        sAhi[BUF][ai] = hi; sAlo[BUF][ai] = lo;                                   \
        split_pack(pa[q].z, pa[q].w, hi, lo);                                     \
        sAhi[BUF][ai + 1] = hi; sAlo[BUF][ai + 1] = lo;                           \
        int bc4 = ((tid & 7) + 8 * q) << 2;                                       \
        int bi = (ar * SBW + bc4) >> 1;                                           \
        split_pack(pb[q].x, pb[q].y, hi, lo);                                     \
        sBhi[BUF][bi] = hi; sBlo[BUF][bi] = lo;                                   \
        split_pack(pb[q].z, pb[q].w, hi, lo);                                     \
        sBhi[BUF][bi + 1] = hi; sBlo[BUF][bi + 1] = lo;                           \
    }                                                                             \
} while (0)

__global__ void __launch_bounds__(256, 1)
k_gemm1(const float* __restrict__ x, const float* __restrict__ w,
        const float* __restrict__ wu, const float* __restrict__ wv) {
    __shared__ unsigned sAhi[2][BM * SA / 2];
    __shared__ unsigned sAlo[2][BM * SA / 2];
    __shared__ unsigned sBhi[2][BK * SBW / 2];
    __shared__ unsigned sBlo[2][BK * SBW / 2];

    const int tid = threadIdx.x;
    const int lane = tid & 31;
    const int wp = tid >> 5;
    const int wm = (wp & 1) * 64;
    const int wn = (wp >> 1) * 32;
    const int m0 = blockIdx.x * BM;

    const unsigned aHiB = smem_u32(sAhi);
    const unsigned aLoB = smem_u32(sAlo);
    const unsigned bHiB = smem_u32(sBhi);
    const unsigned bLoB = smem_u32(sBlo);

    const int i8 = lane >> 3;
    const int w8 = lane & 7;

    const int ar = tid >> 3;
    const int ac4 = (tid & 7) << 2;

    float acc[2][4][4];
    float acc2[2][4][4];
#pragma unroll
    for (int i = 0; i < 2; i++)
#pragma unroll
        for (int j = 0; j < 4; j++)
#pragma unroll
            for (int k = 0; k < 4; k++) { acc[i][j][k] = 0.f; acc2[i][j][k] = 0.f; }

    float4 pa[4], pb[4];
    const int NT = NF / BK;   // 16

    LOAD_REGS(0);
    STORE_STAGE(0);
    __syncthreads();

    for (int kt = 0; kt < NT; kt++) {
        const int buf = kt & 1;
        const unsigned aOff = buf ? (unsigned)ABY : 0u;
        const unsigned bOff = buf ? (unsigned)BBY : 0u;

        if (kt + 1 < NT) LOAD_REGS(kt + 1);

#pragma unroll
        for (int ks = 0; ks < 2; ks++) {
            int k0 = ks * 16;
            unsigned bh[4][2], bl[4][2];
            int brow = k0 + ((i8 & 1) << 3) + w8;
#pragma unroll
            for (int p = 0; p < 2; p++) {
                int bcol = wn + p * 16 + ((i8 >> 1) << 3);
                unsigned off = (unsigned)(brow * SBW + bcol) * 2u + bOff;
                ldsm_x4_t(bh[2 * p][0], bh[2 * p][1], bh[2 * p + 1][0], bh[2 * p + 1][1],
                          bHiB + off);
                ldsm_x4_t(bl[2 * p][0], bl[2 * p][1], bl[2 * p + 1][0], bl[2 * p + 1][1],
                          bLoB + off);
            }
#pragma unroll
            for (int mh = 0; mh < 2; mh++) {
#pragma unroll
                for (int mt = 0; mt < 2; mt++) {
                    int arow = wm + (mh * 2 + mt) * 16 + ((i8 & 1) << 3) + w8;
                    int acol = k0 + ((i8 >> 1) << 3);
                    unsigned off = (unsigned)(arow * SA + acol) * 2u + aOff;
                    unsigned ah[4], al[4];
                    ldsm_x4(ah[0], ah[1], ah[2], ah[3], aHiB + off);
                    ldsm_x4(al[0], al[1], al[2], al[3], aLoB + off);
                    float* accp0;
#pragma unroll
                    for (int nt = 0; nt < 4; nt++) {
                        accp0 = mh ? acc2[mt][nt] : acc[mt][nt];
                        mma_bf16(accp0, ah, bh[nt]);
                        mma_bf16(accp0, ah, bl[nt]);
                        mma_bf16(accp0, al, bh[nt]);
                    }
                }
            }
        }

        if (kt + 1 < NT) {
            STORE_STAGE(buf ^ 1);
            __syncthreads();
        }
    }

    // epilogue: store h1 + fused el1/er1 partials
#pragma unroll
    for (int mh = 0; mh < 2; mh++) {
#pragma unroll
        for (int mt = 0; mt < 2; mt++) {
            int r0 = m0 + wm + (mh * 2 + mt) * 16 + (lane >> 2);
            int r1 = r0 + 8;
            float pu0 = 0.f, pv0 = 0.f, pu1 = 0.f, pv1 = 0.f;
#pragma unroll
            for (int nt = 0; nt < 4; nt++) {
                const float* ac = mh ? acc2[mt][nt] : acc[mt][nt];
                int col = wn + nt * 8 + ((lane & 3) << 1);
                float u0 = wu[col], u1 = wu[col + 1];
                float v0 = wv[col], v1 = wv[col + 1];
                float l00 = leakyf(ac[0]), l01 = leakyf(ac[1]);
                float l10 = leakyf(ac[2]), l11 = leakyf(ac[3]);
                pu0 += l00 * u0 + l01 * u1;
                pv0 += l00 * v0 + l01 * v1;
                pu1 += l10 * u0 + l11 * u1;
                pv1 += l10 * v0 + l11 * v1;
                if (r0 < NN)
                    *(float2*)&g_h1[(size_t)r0 * NH + col] = make_float2(ac[0], ac[1]);
                if (r1 < NN)
                    *(float2*)&g_h1[(size_t)r1 * NH + col] = make_float2(ac[2], ac[3]);
            }
            pu0 += __shfl_down_sync(0xffffffffu, pu0, 2, 4);
            pu0 += __shfl_down_sync(0xffffffffu, pu0, 1, 4);
            pv0 += __shfl_down_sync(0xffffffffu, pv0, 2, 4);
            pv0 += __shfl_down_sync(0xffffffffu, pv0, 1, 4);
            pu1 += __shfl_down_sync(0xffffffffu, pu1, 2, 4);
            pu1 += __shfl_down_sync(0xffffffffu, pu1, 1, 4);
            pv1 += __shfl_down_sync(0xffffffffu, pv1, 2, 4);
            pv1 += __shfl_down_sync(0xffffffffu, pv1, 1, 4);
            if ((lane & 3) == 0) {
                if (r0 < NN) { atomicAdd(&g_el1[r0], pu0); atomicAdd(&g_er1[r0], pv0); }
                if (r1 < NN) { atomicAdd(&g_el1[r1], pu1); atomicAdd(&g_er1[r1], pv1); }
            }
        }
    }
}

// ---------------- layer1 edge pass A: 16-lane edge groups ----------------
__global__ void k_edgeA1(const int* __restrict__ src, const int* __restrict__ dst,
                         const float* __restrict__ ws1) {
    int gt = blockIdx.x * blockDim.x + threadIdx.x;
    int l = threadIdx.x & 15;
    int grp = gt >> 4;
    int ngr = (gridDim.x * blockDim.x) >> 4;
    float wsv = ws1[l];
    float bw = g_scal[0];
    float bw0 = bw * g_scal[1], bw1 = bw * g_scal[2];

    for (int e = grp; e < EE; e += ngr) {
        int s = src[e], d = dst[e];
        const float4* as = (const float4*)(g_h1 + (size_t)s * NH);
        const float4* ad = (const float4*)(g_h1 + (size_t)d * NH);
        float4 a0 = as[2 * l], a1 = as[2 * l + 1];
        float4 b0 = ad[2 * l], b1 = ad[2 * l + 1];
        float d0 = a0.x - b0.x, d1 = a0.y - b0.y, d2 = a0.z - b0.z, d3 = a0.w - b0.w;
        float d4 = a1.x - b1.x, d5 = a1.y - b1.y, d6 = a1.z - b1.z, d7 = a1.w - b1.w;
        float sdf = d0 * d0 + d1 * d1 + d2 * d2 + d3 * d3
                  + d4 * d4 + d5 * d5 + d6 * d6 + d7 * d7;
        float ps = g_hlatp[(size_t)s * NC + l];
        float pd = g_hlatp[(size_t)d * NC + l];
        float df = ps - pd;
        float sds = df * df;
        float st = ps * wsv * pd;
#pragma unroll
        for (int off = 8; off; off >>= 1) {
            sdf += __shfl_down_sync(0xffffffffu, sdf, off, 16);
            sds += __shfl_down_sync(0xffffffffu, sds, off, 16);
            st  += __shfl_down_sync(0xffffffffu, st, off, 16);
        }
        if (l == 0) {
            float ee = g_el1[s] + g_er1[d] + st;
            float ew = expf(ee - bw0 * sdf - bw1 * sds) + EPSF;
            g_ew1[e] = ew;
            atomicAdd(&g_outw1[s], ew);
            atomicAdd(&g_inw1[d], ew);
            atomicAdd(&g_indeg[d], 1.0f);
        }
    }
}

// ---------------- CSR build: scan indeg -> offsets ----------------
#define SB 1024
__global__ void k_scan1() {
    __shared__ int s[SB];
    int t = threadIdx.x;
    int i = blockIdx.x * SB + t;
    int v = (i < NN) ? (int)g_indeg[i] : 0;
    s[t] = v;
    __syncthreads();
    for (int off = 1; off < SB; off <<= 1) {
        int xv = (t >= off) ? s[t - off] : 0;
        __syncthreads();
        if (t >= off) s[t] += xv;
        __syncthreads();
    }
    if (i < NN) g_exc[i] = s[t] - v;
    if (t == SB - 1) g_bsum[blockIdx.x] = s[t];
}

__global__ void k_scan2(int nb) {
    __shared__ int s[64];
    int t = threadIdx.x;
    int v = (t < nb) ? g_bsum[t] : 0;
    s[t] = v;
    __syncthreads();
    for (int off = 1; off < 64; off <<= 1) {
        int xv = (t >= off) ? s[t - off] : 0;
        __syncthreads();
        if (t >= off) s[t] += xv;
        __syncthreads();
    }
    g_bexc[t] = s[t] - v;
}

__global__ void k_scan3() {
    int i = blockIdx.x * blockDim.x + threadIdx.x;
    if (i < NN) {
        int st = g_exc[i] + g_bexc[i >> 10];
        g_start[i] = st;
        g_cursor[i] = st;
    }
}

// ---------------- scatter: csr_src + precombined weight ----------------
__global__ void k_scatter(const int* __restrict__ src, const int* __restrict__ dst) {
    int e = blockIdx.x * blockDim.x + threadIdx.x;
    if (e < EE) {
        int s = src[e];
        int p = atomicAdd(&g_cursor[dst[e]], 1);
        g_csrc[p] = s;
        g_cw[p] = rsqrtf(g_outw1[s]) * g_ew1[e];
    }
}

// ---------------- layer1 aggregation: CSR gather, fused combine+elu -> g_h ----------------
__global__ void k_aggr1() {
    int gt = blockIdx.x * blockDim.x + threadIdx.x;
    int lane = threadIdx.x & 31;
    int wid = gt >> 5;
    int nw = (gridDim.x * blockDim.x) >> 5;
    float pc = g_scal[3];
    for (int n = wid; n < NN; n += nw) {
        int st = g_start[n];
        int deg = (int)g_indeg[n];
        float invin = (deg > 0) ? rsqrtf(g_inw1[n]) : 0.f;
        float4 acc = make_float4(0.f, 0.f, 0.f, 0.f);
        int j = 0;
        for (; j + 2 <= deg; j += 2) {
            int s0 = g_csrc[st + j], s1 = g_csrc[st + j + 1];
            float w0 = g_cw[st + j], w1 = g_cw[st + j + 1];
            float4 h0 = ((const float4*)(g_h1 + (size_t)s0 * NH))[lane];
            float4 h1v = ((const float4*)(g_h1 + (size_t)s1 * NH))[lane];
            acc.x += h0.x * w0 + h1v.x * w1;
            acc.y += h0.y * w0 + h1v.y * w1;
            acc.z += h0.z * w0 + h1v.z * w1;
            acc.w += h0.w * w0 + h1v.w * w1;
        }
        if (j < deg) {
            int s0 = g_csrc[st + j];
            float w0 = g_cw[st + j];
            float4 h0 = ((const float4*)(g_h1 + (size_t)s0 * NH))[lane];
            acc.x += h0.x * w0; acc.y += h0.y * w0;
            acc.z += h0.z * w0; acc.w += h0.w * w0;
        }
        float perm = pc / ((float)deg + EPSF);
        float4 hn = ((const float4*)(g_h1 + (size_t)n * NH))[lane];
        float4 o;
        o.x = eluf(acc.x * invin + hn.x * perm);
        o.y = eluf(acc.y * invin + hn.y * perm);
        o.z = eluf(acc.z * invin + hn.z * perm);
        o.w = eluf(acc.w * invin + hn.w * perm);
        ((float4*)(g_h + (size_t)n * NH))[lane] = o;
    }
}

// ---------------- h2 = h @ fc2_w ; el2/er2 ----------------
__global__ void k_fc2(const float* __restrict__ w, const float* __restrict__ wu,
                      const float* __restrict__ wv) {
    __shared__ float Ws[NH * NC];
    __shared__ float Hrow[8][NH];
    int t = threadIdx.x;
    for (int j = t; j < NH * NC; j += blockDim.x) Ws[j] = w[j];
    __syncthreads();

    int lane = t & 31;
    int wid = t >> 5;
    int c = lane & 15;
    int half = lane >> 4;
    int gw = (blockIdx.x * blockDim.x + t) >> 5;
    int nw = (gridDim.x * blockDim.x) >> 5;
    float wuc = wu[c], wvc = wv[c];

    for (int n = gw; n < NN; n += nw) {
        float4 hh = ((const float4*)(g_h + (size_t)n * NH))[lane];
        *(float4*)&Hrow[wid][lane << 2] = hh;
        __syncwarp();

        float acc = 0.f;
        int kb = half * 64;
#pragma unroll
        for (int k = 0; k < 64; k++) acc += Hrow[wid][kb + k] * Ws[(kb + k) * NC + c];
        acc += __shfl_xor_sync(0xffffffffu, acc, 16);
        if (half == 0) g_h2[(size_t)n * NC + c] = acc;
        float lr = leakyf(acc);
        float pu = lr * wuc, pv = lr * wvc;
#pragma unroll
        for (int off = 8; off; off >>= 1) {
            pu += __shfl_down_sync(0xffffffffu, pu, off, 16);
            pv += __shfl_down_sync(0xffffffffu, pv, off, 16);
        }
        if (lane == 0) { g_el2[n] = pu; g_er2[n] = pv; }
        __syncwarp();
    }
}

// ---------------- layer2 edge pass A ----------------
__global__ void k_edgeA2(const int* __restrict__ src, const int* __restrict__ dst,
                         const float* __restrict__ ws2, const float* __restrict__ wts) {
    __shared__ float redbuf[256];
    int t = threadIdx.x;
    int c = t & 15;
    int grp = (blockIdx.x * blockDim.x + t) >> 4;
    int ngr = (gridDim.x * blockDim.x) >> 4;
    float wsv = ws2[c];
    float bw = g_scal[4], w0 = g_scal[5], w1 = g_scal[6];
    float lpacc = 0.f;

    for (int e = grp; e < EE; e += ngr) {
        int s = src[e], d = dst[e];
        float hs = g_h2[(size_t)s * NC + c], hd = g_h2[(size_t)d * NC + c];
        float ps = g_hlatp2[(size_t)s * NC + c], pd = g_hlatp2[(size_t)d * NC + c];
        float df = hs - hd;
        float sdf = df * df;
        float dp = ps - pd;
        float sds = dp * dp;
        float prod = ps * pd;
        float st = prod * wsv;
#pragma unroll
        for (int off = 8; off; off >>= 1) {
            sdf  += __shfl_down_sync(0xffffffffu, sdf, off, 16);
            sds  += __shfl_down_sync(0xffffffffu, sds, off, 16);
            st   += __shfl_down_sync(0xffffffffu, st, off, 16);
            prod += __shfl_down_sync(0xffffffffu, prod, off, 16);
        }
        if (c == 0) {
            float ee = g_el2[s] + g_er2[d] + st;
            float ew = expf(ee - bw * (w0 * sdf + w1 * sds)) + EPSF;
            g_ew2[e] = ew;
            atomicAdd(&g_outw2[s], ew);
            atomicAdd(&g_inw2[d], ew);
            lpacc += wts[e] * prod;
        }
    }
    redbuf[t] = lpacc;
    __syncthreads();
    for (int s2 = 128; s2; s2 >>= 1) {
        if (t < s2) redbuf[t] += redbuf[t + s2];
        __syncthreads();
    }
    if (t == 0) atomicAdd(&g_lp, redbuf[0]);
}

// ---------------- layer2 edge pass B ----------------
__global__ void k_edgeB2(const int* __restrict__ src, const int* __restrict__ dst) {
    int gt = blockIdx.x * blockDim.x + threadIdx.x;
    int sub = gt & 3;
    int grp = gt >> 2;
    int ngr = (gridDim.x * blockDim.x) >> 2;
    for (int e = grp; e < EE; e += ngr) {
        int s = src[e], d = dst[e];
        float a = rsqrtf(g_outw2[s]) * rsqrtf(g_inw2[d]) * g_ew2[e];
        float4 h = ((const float4*)(g_h2 + (size_t)s * NC))[sub];
        h.x *= a; h.y *= a; h.z *= a; h.w *= a;
        red_add_v4(&g_rst2[(size_t)d * NC + (sub << 2)], h);
    }
}

// ---------------- final ----------------
__global__ void k_final(float* __restrict__ out, int out_size) {
    int t = threadIdx.x;
    int c = t & 15;
    int grp = (blockIdx.x * blockDim.x + t) >> 4;
    int ngr = (gridDim.x * blockDim.x) >> 4;
    float pc = g_scal[7];

    for (int n = grp; n < NN; n += ngr) {
        float perm = pc / (g_indeg[n] + EPSF);
        float v = g_rst2[(size_t)n * NC + c] + g_h2[(size_t)n * NC + c] * perm;
        float xv = eluf(v);
        float m = xv;
#pragma unroll
        for (int off = 8; off; off >>= 1)
            m = fmaxf(m, __shfl_xor_sync(0xffffffffu, m, off, 16));
        float ex = expf(xv - m);
        float ssum = ex;
#pragma unroll
        for (int off = 8; off; off >>= 1)
            ssum += __shfl_xor_sync(0xffffffffu, ssum, off, 16);
        out[(size_t)n * NC + c] = xv - m - logf(ssum);
    }
    if (blockIdx.x == 0 && t == 0 && out_size > NN * NC)
        out[NN * NC] = g_lp;
}

// ---------------- launch ----------------
extern "C" void kernel_launch(void* const* d_in, const int* in_sizes, int n_in,
                              void* d_out, int out_size) {
    const int*   src    = (const int*)d_in[0];
    const int*   dst    = (const int*)d_in[1];
    const float* x      = (const float*)d_in[2];
    const float* wts    = (const float*)d_in[3];
    const float* latp   = (const float*)d_in[4];
    const float* sl_w   = (const float*)d_in[5];
    const float* sl_b   = (const float*)d_in[6];
    const float* slo_w  = (const float*)d_in[7];
    const float* slo_b  = (const float*)d_in[8];
    const float* fc1_w  = (const float*)d_in[9];
    const float* w_u1   = (const float*)d_in[10];
    const float* w_v1   = (const float*)d_in[11];
    const float* w_s1   = (const float*)d_in[12];
    const float* beta1  = (const float*)d_in[13];
    const float* aw1    = (const float*)d_in[14];
    const float* theta1 = (const float*)d_in[15];
    const float* fc2_w  = (const float*)d_in[16];
    const float* w_u2   = (const float*)d_in[17];
    const float* w_v2   = (const float*)d_in[18];
    const float* w_s2   = (const float*)d_in[19];
    const float* beta2  = (const float*)d_in[20];
    const float* aw2    = (const float*)d_in[21];
    const float* theta2 = (const float*)d_in[22];
    float* out = (float*)d_out;

    int nb_scan = (NN + SB - 1) / SB;   // 49

    k_zero<<<512, 256>>>();
    k_scalars<<<1, 32>>>(beta1, aw1, theta1, beta2, aw2, theta2);
    k_latp<<<(NN + 255) / 256, 256>>>(latp, sl_w, sl_b, slo_w, slo_b);
    k_gemm1<<<(NN + BM - 1) / BM, 256>>>(x, fc1_w, w_u1, w_v1);
    k_edgeA1<<<4096, 256>>>(src, dst, w_s1);
    k_scan1<<<nb_scan, SB>>>();
    k_scan2<<<1, 64>>>(nb_scan);
    k_scan3<<<(NN + 255) / 256, 256>>>();
    k_scatter<<<(EE + 255) / 256, 256>>>(src, dst);
    k_aggr1<<<6250, 256>>>();
    k_fc2<<<2048, 256>>>(fc2_w, w_u2, w_v2);
    k_edgeA2<<<2048, 256>>>(src, dst, w_s2, wts);
    k_edgeB2<<<2048, 256>>>(src, dst);
    k_final<<<2048, 256>>>(out, out_size);
}

// round 14
// speedup vs baseline: 1.1235x; 1.0364x over previous
#include <cuda_runtime.h>
#include <math.h>

#define NN 50000
#define EE 800000
#define NF  512
#define NH  128
#define NC  16
#define EPSF 1e-9f

// ---------------- scratch (static device allocations) ----------------
__device__ float g_h1[NN * NH];
__device__ float g_hlatp[NN * NC];
__device__ float g_hlatp2[NN * NC];
__device__ float g_h2[NN * NC];
__device__ float g_el1[NN], g_er1[NN];
__device__ float g_el2[NN], g_er2[NN];
__device__ float g_indeg[NN];
__device__ float g_outw1[NN], g_inw1[NN], g_outw2[NN], g_inw2[NN];
__device__ float g_ew1[EE], g_ew2[EE];
__device__ float g_lp;
__device__ float g_scal[8];
// CSR
__device__ int g_exc[NN];
__device__ int g_bsum[64];
__device__ int g_bexc[64];
__device__ int g_start[NN];
__device__ int g_cursor[NN];
__device__ int g_csrc[EE];
__device__ int g_eid[EE];
__device__ float g_cw[EE];
__device__ float g_cw2[EE];

// ---------------- helpers ----------------
__device__ __forceinline__ float eluf(float x) { return x > 0.f ? x : expm1f(x); }
__device__ __forceinline__ float leakyf(float x) { return x > 0.f ? x : 0.2f * x; }

__device__ __forceinline__ unsigned smem_u32(const void* p) {
    unsigned r;
    asm("{ .reg .u64 t; cvta.to.shared.u64 t, %1; cvt.u32.u64 %0, t; }"
        : "=r"(r) : "l"(p));
    return r;
}

__device__ __forceinline__ unsigned pack_bf16(float a, float b) {
    unsigned r;
    asm("cvt.rn.bf16x2.f32 %0, %1, %2;" : "=r"(r) : "f"(b), "f"(a));
    return r;
}
__device__ __forceinline__ float bf16lo_f(unsigned p) { return __uint_as_float(p << 16); }
__device__ __forceinline__ float bf16hi_f(unsigned p) { return __uint_as_float(p & 0xffff0000u); }

__device__ __forceinline__ void ldsm_x4(unsigned& r0, unsigned& r1, unsigned& r2, unsigned& r3,
                                        unsigned addr) {
    asm volatile("ldmatrix.sync.aligned.m8n8.x4.shared.b16 {%0,%1,%2,%3}, [%4];"
                 : "=r"(r0), "=r"(r1), "=r"(r2), "=r"(r3) : "r"(addr));
}
__device__ __forceinline__ void ldsm_x4_t(unsigned& r0, unsigned& r1, unsigned& r2, unsigned& r3,
                                          unsigned addr) {
    asm volatile("ldmatrix.sync.aligned.m8n8.x4.trans.shared.b16 {%0,%1,%2,%3}, [%4];"
                 : "=r"(r0), "=r"(r1), "=r"(r2), "=r"(r3) : "r"(addr));
}
__device__ __forceinline__ void mma_bf16(float* c, const unsigned* a, const unsigned* b) {
    asm volatile(
        "mma.sync.aligned.m16n8k16.row.col.f32.bf16.bf16.f32 "
        "{%0,%1,%2,%3}, {%4,%5,%6,%7}, {%8,%9}, {%0,%1,%2,%3};"
        : "+f"(c[0]), "+f"(c[1]), "+f"(c[2]), "+f"(c[3])
        : "r"(a[0]), "r"(a[1]), "r"(a[2]), "r"(a[3]), "r"(b[0]), "r"(b[1]));
}

__device__ __forceinline__ void split_pack(float v0, float v1, unsigned& hi, unsigned& lo) {
    hi = pack_bf16(v0, v1);
    float h0 = bf16lo_f(hi);
    float h1 = bf16hi_f(hi);
    lo = pack_bf16(v0 - h0, v1 - h1);
}

// ---------------- zero scratch ----------------
__global__ void k_zero() {
    int i = blockIdx.x * blockDim.x + threadIdx.x;
    int st = gridDim.x * blockDim.x;
    for (int j = i; j < NN; j += st) {
        g_indeg[j] = 0.f;
        g_outw1[j] = 0.f; g_inw1[j] = 0.f;
        g_outw2[j] = 0.f; g_inw2[j] = 0.f;
        g_el1[j] = 0.f; g_er1[j] = 0.f;
    }
    if (i == 0) g_lp = 0.f;
}

// ---------------- derived scalars ----------------
__global__ void k_scalars(const float* beta1, const float* aw1, const float* theta1,
                          const float* beta2, const float* aw2, const float* theta2) {
    if (threadIdx.x == 0) {
        g_scal[0] = 2.f / (expf(-beta1[0]) + 1.f);
        float m1 = fmaxf(aw1[0], aw1[1]);
        float a0 = expf(aw1[0] - m1), a1 = expf(aw1[1] - m1);
        g_scal[1] = a0 / (a0 + a1);
        g_scal[2] = a1 / (a0 + a1);
        g_scal[3] = EPSF / (expf(-theta1[0]) + 1.f);

        g_scal[4] = 2.f / (expf(-beta2[0]) + 1.f);
        float m2 = fmaxf(aw2[0], aw2[1]);
        float b0 = expf(aw2[0] - m2), b1 = expf(aw2[1] - m2);
        g_scal[5] = b0 / (b0 + b1);
        g_scal[6] = b1 / (b0 + b1);
        g_scal[7] = EPSF / (expf(-theta2[0]) + 1.f);
    }
}

// ---------------- hlatp / hlatp2 ----------------
__global__ void k_latp(const float* __restrict__ latp,
                       const float* __restrict__ sl_w, const float* __restrict__ sl_b,
                       const float* __restrict__ slo_w, const float* __restrict__ slo_b) {
    __shared__ float W1[NC * NC], W2[NC * NC], B1[NC], B2[NC];
    int t = threadIdx.x;
    if (t < NC * NC) { W1[t] = sl_w[t]; W2[t] = slo_w[t]; }
    if (t < NC) { B1[t] = sl_b[t]; B2[t] = slo_b[t]; }
    __syncthreads();
    int n = blockIdx.x * blockDim.x + t;
    if (n >= NN) return;

    float in[NC], t1[NC];
#pragma unroll
    for (int j = 0; j < NC; j++) in[j] = latp[n * NC + j];
#pragma unroll
    for (int c = 0; c < NC; c++) {
        float acc = B1[c];
#pragma unroll
        for (int j = 0; j < NC; j++) acc += in[j] * W1[j * NC + c];
        t1[c] = eluf(acc);
        g_hlatp[n * NC + c] = t1[c];
    }
#pragma unroll
    for (int c = 0; c < NC; c++) {
        float acc = B2[c];
#pragma unroll
        for (int j = 0; j < NC; j++) acc += t1[j] * W2[j * NC + c];
        g_hlatp2[n * NC + c] = eluf(acc);
    }
}

// ---------------- tensor GEMM: h1 = x @ fc1_w, bf16 split, double-buffered ----------------
#define BM 128
#define BN 128
#define BK 32
#define SA 40
#define SBW 136
#define ABY (BM * SA * 2)
#define BBY (BK * SBW * 2)

#define LOAD_REGS(KT) do {                                                        \
    int kbase = (KT) * BK;                                                        \
    _Pragma("unroll")                                                             \
    for (int q = 0; q < 4; q++) {                                                 \
        int gm = m0 + ar + 32 * q;                                                \
        if (gm < NN) pa[q] = *(const float4*)(x + (size_t)gm * NF + kbase + ac4); \
        else pa[q] = make_float4(0.f, 0.f, 0.f, 0.f);                             \
        int bc4 = ((tid & 7) + 8 * q) << 2;                                       \
        pb[q] = *(const float4*)(w + (size_t)(kbase + ar) * BN + bc4);            \
    }                                                                             \
} while (0)

#define STORE_STAGE(BUF) do {                                                     \
    _Pragma("unroll")                                                             \
    for (int q = 0; q < 4; q++) {                                                 \
        int r = ar + 32 * q;                                                      \
        unsigned hi, lo;                                                          \
        int ai = (r * SA + ac4) >> 1;                                             \
        split_pack(pa[q].x, pa[q].y, hi, lo);                                     \
        sAhi[BUF][ai] = hi; sAlo[BUF][ai] = lo;                                   \
        split_pack(pa[q].z, pa[q].w, hi, lo);                                     \
        sAhi[BUF][ai + 1] = hi; sAlo[BUF][ai + 1] = lo;                           \
        int bc4 = ((tid & 7) + 8 * q) << 2;                                       \
        int bi = (ar * SBW + bc4) >> 1;                                           \
        split_pack(pb[q].x, pb[q].y, hi, lo);                                     \
        sBhi[BUF][bi] = hi; sBlo[BUF][bi] = lo;                                   \
        split_pack(pb[q].z, pb[q].w, hi, lo);                                     \
        sBhi[BUF][bi + 1] = hi; sBlo[BUF][bi + 1] = lo;                           \
    }                                                                             \
} while (0)

__global__ void __launch_bounds__(256, 1)
k_gemm1(const float* __restrict__ x, const float* __restrict__ w,
        const float* __restrict__ wu, const float* __restrict__ wv) {
    __shared__ unsigned sAhi[2][BM * SA / 2];
    __shared__ unsigned sAlo[2][BM * SA / 2];
    __shared__ unsigned sBhi[2][BK * SBW / 2];
    __shared__ unsigned sBlo[2][BK * SBW / 2];

    const int tid = threadIdx.x;
    const int lane = tid & 31;
    const int wp = tid >> 5;
    const int wm = (wp & 1) * 64;
    const int wn = (wp >> 1) * 32;
    const int m0 = blockIdx.x * BM;

    const unsigned aHiB = smem_u32(sAhi);
    const unsigned aLoB = smem_u32(sAlo);
    const unsigned bHiB = smem_u32(sBhi);
    const unsigned bLoB = smem_u32(sBlo);

    const int i8 = lane >> 3;
    const int w8 = lane & 7;

    const int ar = tid >> 3;
    const int ac4 = (tid & 7) << 2;

    float acc[2][4][4];
    float acc2[2][4][4];
#pragma unroll
    for (int i = 0; i < 2; i++)
#pragma unroll
        for (int j = 0; j < 4; j++)
#pragma unroll
            for (int k = 0; k < 4; k++) { acc[i][j][k] = 0.f; acc2[i][j][k] = 0.f; }

    float4 pa[4], pb[4];
    const int NT = NF / BK;   // 16

    LOAD_REGS(0);
    STORE_STAGE(0);
    __syncthreads();

    for (int kt = 0; kt < NT; kt++) {
        const int buf = kt & 1;
        const unsigned aOff = buf ? (unsigned)ABY : 0u;
        const unsigned bOff = buf ? (unsigned)BBY : 0u;

        if (kt + 1 < NT) LOAD_REGS(kt + 1);

#pragma unroll
        for (int ks = 0; ks < 2; ks++) {
            int k0 = ks * 16;
            unsigned bh[4][2], bl[4][2];
            int brow = k0 + ((i8 & 1) << 3) + w8;
#pragma unroll
            for (int p = 0; p < 2; p++) {
                int bcol = wn + p * 16 + ((i8 >> 1) << 3);
                unsigned off = (unsigned)(brow * SBW + bcol) * 2u + bOff;
                ldsm_x4_t(bh[2 * p][0], bh[2 * p][1], bh[2 * p + 1][0], bh[2 * p + 1][1],
                          bHiB + off);
                ldsm_x4_t(bl[2 * p][0], bl[2 * p][1], bl[2 * p + 1][0], bl[2 * p + 1][1],
                          bLoB + off);
            }
#pragma unroll
            for (int mh = 0; mh < 2; mh++) {
#pragma unroll
                for (int mt = 0; mt < 2; mt++) {
                    int arow = wm + (mh * 2 + mt) * 16 + ((i8 & 1) << 3) + w8;
                    int acol = k0 + ((i8 >> 1) << 3);
                    unsigned off = (unsigned)(arow * SA + acol) * 2u + aOff;
                    unsigned ah[4], al[4];
                    ldsm_x4(ah[0], ah[1], ah[2], ah[3], aHiB + off);
                    ldsm_x4(al[0], al[1], al[2], al[3], aLoB + off);
                    float* accp0;
#pragma unroll
                    for (int nt = 0; nt < 4; nt++) {
                        accp0 = mh ? acc2[mt][nt] : acc[mt][nt];
                        mma_bf16(accp0, ah, bh[nt]);
                        mma_bf16(accp0, ah, bl[nt]);
                        mma_bf16(accp0, al, bh[nt]);
                    }
                }
            }
        }

        if (kt + 1 < NT) {
            STORE_STAGE(buf ^ 1);
            __syncthreads();
        }
    }

    // epilogue: store h1 + fused el1/er1 partials
#pragma unroll
    for (int mh = 0; mh < 2; mh++) {
#pragma unroll
        for (int mt = 0; mt < 2; mt++) {
            int r0 = m0 + wm + (mh * 2 + mt) * 16 + (lane >> 2);
            int r1 = r0 + 8;
            float pu0 = 0.f, pv0 = 0.f, pu1 = 0.f, pv1 = 0.f;
#pragma unroll
            for (int nt = 0; nt < 4; nt++) {
                const float* ac = mh ? acc2[mt][nt] : acc[mt][nt];
                int col = wn + nt * 8 + ((lane & 3) << 1);
                float u0 = wu[col], u1 = wu[col + 1];
                float v0 = wv[col], v1 = wv[col + 1];
                float l00 = leakyf(ac[0]), l01 = leakyf(ac[1]);
                float l10 = leakyf(ac[2]), l11 = leakyf(ac[3]);
                pu0 += l00 * u0 + l01 * u1;
                pv0 += l00 * v0 + l01 * v1;
                pu1 += l10 * u0 + l11 * u1;
                pv1 += l10 * v0 + l11 * v1;
                if (r0 < NN)
                    *(float2*)&g_h1[(size_t)r0 * NH + col] = make_float2(ac[0], ac[1]);
                if (r1 < NN)
                    *(float2*)&g_h1[(size_t)r1 * NH + col] = make_float2(ac[2], ac[3]);
            }
            pu0 += __shfl_down_sync(0xffffffffu, pu0, 2, 4);
            pu0 += __shfl_down_sync(0xffffffffu, pu0, 1, 4);
            pv0 += __shfl_down_sync(0xffffffffu, pv0, 2, 4);
            pv0 += __shfl_down_sync(0xffffffffu, pv0, 1, 4);
            pu1 += __shfl_down_sync(0xffffffffu, pu1, 2, 4);
            pu1 += __shfl_down_sync(0xffffffffu, pu1, 1, 4);
            pv1 += __shfl_down_sync(0xffffffffu, pv1, 2, 4);
            pv1 += __shfl_down_sync(0xffffffffu, pv1, 1, 4);
            if ((lane & 3) == 0) {
                if (r0 < NN) { atomicAdd(&g_el1[r0], pu0); atomicAdd(&g_er1[r0], pv0); }
                if (r1 < NN) { atomicAdd(&g_el1[r1], pu1); atomicAdd(&g_er1[r1], pv1); }
            }
        }
    }
}

// ---------------- layer1 edge pass A: 16-lane edge groups ----------------
__global__ void k_edgeA1(const int* __restrict__ src, const int* __restrict__ dst,
                         const float* __restrict__ ws1) {
    int gt = blockIdx.x * blockDim.x + threadIdx.x;
    int l = threadIdx.x & 15;
    int grp = gt >> 4;
    int ngr = (gridDim.x * blockDim.x) >> 4;
    float wsv = ws1[l];
    float bw = g_scal[0];
    float bw0 = bw * g_scal[1], bw1 = bw * g_scal[2];

    for (int e = grp; e < EE; e += ngr) {
        int s = src[e], d = dst[e];
        const float4* as = (const float4*)(g_h1 + (size_t)s * NH);
        const float4* ad = (const float4*)(g_h1 + (size_t)d * NH);
        float4 a0 = as[2 * l], a1 = as[2 * l + 1];
        float4 b0 = ad[2 * l], b1 = ad[2 * l + 1];
        float d0 = a0.x - b0.x, d1 = a0.y - b0.y, d2 = a0.z - b0.z, d3 = a0.w - b0.w;
        float d4 = a1.x - b1.x, d5 = a1.y - b1.y, d6 = a1.z - b1.z, d7 = a1.w - b1.w;
        float sdf = d0 * d0 + d1 * d1 + d2 * d2 + d3 * d3
                  + d4 * d4 + d5 * d5 + d6 * d6 + d7 * d7;
        float ps = g_hlatp[(size_t)s * NC + l];
        float pd = g_hlatp[(size_t)d * NC + l];
        float df = ps - pd;
        float sds = df * df;
        float st = ps * wsv * pd;
#pragma unroll
        for (int off = 8; off; off >>= 1) {
            sdf += __shfl_down_sync(0xffffffffu, sdf, off, 16);
            sds += __shfl_down_sync(0xffffffffu, sds, off, 16);
            st  += __shfl_down_sync(0xffffffffu, st, off, 16);
        }
        if (l == 0) {
            float ee = g_el1[s] + g_er1[d] + st;
            float ew = expf(ee - bw0 * sdf - bw1 * sds) + EPSF;
            g_ew1[e] = ew;
            atomicAdd(&g_outw1[s], ew);
            atomicAdd(&g_inw1[d], ew);
            atomicAdd(&g_indeg[d], 1.0f);
        }
    }
}

// ---------------- CSR build: scan indeg -> offsets ----------------
#define SB 1024
__global__ void k_scan1() {
    __shared__ int s[SB];
    int t = threadIdx.x;
    int i = blockIdx.x * SB + t;
    int v = (i < NN) ? (int)g_indeg[i] : 0;
    s[t] = v;
    __syncthreads();
    for (int off = 1; off < SB; off <<= 1) {
        int xv = (t >= off) ? s[t - off] : 0;
        __syncthreads();
        if (t >= off) s[t] += xv;
        __syncthreads();
    }
    if (i < NN) g_exc[i] = s[t] - v;
    if (t == SB - 1) g_bsum[blockIdx.x] = s[t];
}

__global__ void k_scan2(int nb) {
    __shared__ int s[64];
    int t = threadIdx.x;
    int v = (t < nb) ? g_bsum[t] : 0;
    s[t] = v;
    __syncthreads();
    for (int off = 1; off < 64; off <<= 1) {
        int xv = (t >= off) ? s[t - off] : 0;
        __syncthreads();
        if (t >= off) s[t] += xv;
        __syncthreads();
    }
    g_bexc[t] = s[t] - v;
}

__global__ void k_scan3() {
    int i = blockIdx.x * blockDim.x + threadIdx.x;
    if (i < NN) {
        int st = g_exc[i] + g_bexc[i >> 10];
        g_start[i] = st;
        g_cursor[i] = st;
    }
}

// ---------------- scatter: csrc + layer1 weight + edge id ----------------
__global__ void k_scatter(const int* __restrict__ src, const int* __restrict__ dst) {
    int e = blockIdx.x * blockDim.x + threadIdx.x;
    if (e < EE) {
        int s = src[e];
        int p = atomicAdd(&g_cursor[dst[e]], 1);
        g_csrc[p] = s;
        g_eid[p] = e;
        g_cw[p] = rsqrtf(g_outw1[s]) * g_ew1[e];
    }
}

// ---------------- fused: layer1 CSR aggregation + combine + elu + fc2 + el2/er2 ----------------
__global__ void k_aggrfc(const float* __restrict__ w, const float* __restrict__ wu,
                         const float* __restrict__ wv) {
    __shared__ float Ws[NH * NC];
    __shared__ float Hrow[8][NH];
    int t = threadIdx.x;
    for (int j = t; j < NH * NC; j += blockDim.x) Ws[j] = w[j];
    __syncthreads();

    int lane = t & 31;
    int wid = t >> 5;
    int c = lane & 15;
    int half = lane >> 4;
    int gw = (blockIdx.x * blockDim.x + t) >> 5;
    int nw = (gridDim.x * blockDim.x) >> 5;
    float wuc = wu[c], wvc = wv[c];
    float pc = g_scal[3];

    for (int n = gw; n < NN; n += nw) {
        int st = g_start[n];
        int deg = (int)g_indeg[n];
        float invin = (deg > 0) ? rsqrtf(g_inw1[n]) : 0.f;
        float4 acc = make_float4(0.f, 0.f, 0.f, 0.f);
        int j = 0;
        for (; j + 2 <= deg; j += 2) {
            int s0 = g_csrc[st + j], s1 = g_csrc[st + j + 1];
            float w0 = g_cw[st + j], w1 = g_cw[st + j + 1];
            float4 h0 = ((const float4*)(g_h1 + (size_t)s0 * NH))[lane];
            float4 h1v = ((const float4*)(g_h1 + (size_t)s1 * NH))[lane];
            acc.x += h0.x * w0 + h1v.x * w1;
            acc.y += h0.y * w0 + h1v.y * w1;
            acc.z += h0.z * w0 + h1v.z * w1;
            acc.w += h0.w * w0 + h1v.w * w1;
        }
        if (j < deg) {
            int s0 = g_csrc[st + j];
            float w0 = g_cw[st + j];
            float4 h0 = ((const float4*)(g_h1 + (size_t)s0 * NH))[lane];
            acc.x += h0.x * w0; acc.y += h0.y * w0;
            acc.z += h0.z * w0; acc.w += h0.w * w0;
        }
        float perm = pc / ((float)deg + EPSF);
        float4 hn = ((const float4*)(g_h1 + (size_t)n * NH))[lane];
        float4 o;
        o.x = eluf(acc.x * invin + hn.x * perm);
        o.y = eluf(acc.y * invin + hn.y * perm);
        o.z = eluf(acc.z * invin + hn.z * perm);
        o.w = eluf(acc.w * invin + hn.w * perm);
        *(float4*)&Hrow[wid][lane << 2] = o;
        __syncwarp();

        float acc2 = 0.f;
        int kb = half * 64;
#pragma unroll
        for (int k = 0; k < 64; k++) acc2 += Hrow[wid][kb + k] * Ws[(kb + k) * NC + c];
        acc2 += __shfl_xor_sync(0xffffffffu, acc2, 16);
        if (half == 0) g_h2[(size_t)n * NC + c] = acc2;
        float lr = leakyf(acc2);
        float pu = lr * wuc, pv = lr * wvc;
#pragma unroll
        for (int off = 8; off; off >>= 1) {
            pu += __shfl_down_sync(0xffffffffu, pu, off, 16);
            pv += __shfl_down_sync(0xffffffffu, pv, off, 16);
        }
        if (lane == 0) { g_el2[n] = pu; g_er2[n] = pv; }
        __syncwarp();
    }
}

// ---------------- layer2 edge pass A ----------------
__global__ void k_edgeA2(const int* __restrict__ src, const int* __restrict__ dst,
                         const float* __restrict__ ws2, const float* __restrict__ wts) {
    __shared__ float redbuf[256];
    int t = threadIdx.x;
    int c = t & 15;
    int grp = (blockIdx.x * blockDim.x + t) >> 4;
    int ngr = (gridDim.x * blockDim.x) >> 4;
    float wsv = ws2[c];
    float bw = g_scal[4], w0 = g_scal[5], w1 = g_scal[6];
    float lpacc = 0.f;

    for (int e = grp; e < EE; e += ngr) {
        int s = src[e], d = dst[e];
        float hs = g_h2[(size_t)s * NC + c], hd = g_h2[(size_t)d * NC + c];
        float ps = g_hlatp2[(size_t)s * NC + c], pd = g_hlatp2[(size_t)d * NC + c];
        float df = hs - hd;
        float sdf = df * df;
        float dp = ps - pd;
        float sds = dp * dp;
        float prod = ps * pd;
        float st = prod * wsv;
#pragma unroll
        for (int off = 8; off; off >>= 1) {
            sdf  += __shfl_down_sync(0xffffffffu, sdf, off, 16);
            sds  += __shfl_down_sync(0xffffffffu, sds, off, 16);
            st   += __shfl_down_sync(0xffffffffu, st, off, 16);
            prod += __shfl_down_sync(0xffffffffu, prod, off, 16);
        }
        if (c == 0) {
            float ee = g_el2[s] + g_er2[d] + st;
            float ew = expf(ee - bw * (w0 * sdf + w1 * sds)) + EPSF;
            g_ew2[e] = ew;
            atomicAdd(&g_outw2[s], ew);
            atomicAdd(&g_inw2[d], ew);
            lpacc += wts[e] * prod;
        }
    }
    redbuf[t] = lpacc;
    __syncthreads();
    for (int s2 = 128; s2; s2 >>= 1) {
        if (t < s2) redbuf[t] += redbuf[t + s2];
        __syncthreads();
    }
    if (t == 0) atomicAdd(&g_lp, redbuf[0]);
}

// ---------------- layer2 CSR coefficients ----------------
__global__ void k_coefp2() {
    int p = blockIdx.x * blockDim.x + threadIdx.x;
    int st = gridDim.x * blockDim.x;
    for (; p < EE; p += st) {
        int s = g_csrc[p];
        int e = g_eid[p];
        g_cw2[p] = rsqrtf(g_outw2[s]) * g_ew2[e];
    }
}

// ---------------- final: layer2 CSR aggregation + combine + elu + log_softmax ----------------
__global__ void k_final(float* __restrict__ out, int out_size) {
    int t = threadIdx.x;
    int c = t & 15;
    int grp = (blockIdx.x * blockDim.x + t) >> 4;
    int ngr = (gridDim.x * blockDim.x) >> 4;
    float pc = g_scal[7];

    for (int n = grp; n < NN; n += ngr) {
        int st = g_start[n];
        int deg = (int)g_indeg[n];
        float invin = (deg > 0) ? rsqrtf(g_inw2[n]) : 0.f;
        float acc = 0.f;
        int j = 0;
        for (; j + 2 <= deg; j += 2) {
            int s0 = g_csrc[st + j], s1 = g_csrc[st + j + 1];
            float w0 = g_cw2[st + j], w1 = g_cw2[st + j + 1];
            acc += w0 * g_h2[(size_t)s0 * NC + c] + w1 * g_h2[(size_t)s1 * NC + c];
        }
        if (j < deg) {
            int s0 = g_csrc[st + j];
            acc += g_cw2[st + j] * g_h2[(size_t)s0 * NC + c];
        }
        float perm = pc / ((float)deg + EPSF);
        float v = acc * invin + g_h2[(size_t)n * NC + c] * perm;
        float xv = eluf(v);
        float m = xv;
#pragma unroll
        for (int off = 8; off; off >>= 1)
            m = fmaxf(m, __shfl_xor_sync(0xffffffffu, m, off, 16));
        float ex = expf(xv - m);
        float ssum = ex;
#pragma unroll
        for (int off = 8; off; off >>= 1)
            ssum += __shfl_xor_sync(0xffffffffu, ssum, off, 16);
        out[(size_t)n * NC + c] = xv - m - logf(ssum);
    }
    if (blockIdx.x == 0 && t == 0 && out_size > NN * NC)
        out[NN * NC] = g_lp;
}

// ---------------- launch ----------------
extern "C" void kernel_launch(void* const* d_in, const int* in_sizes, int n_in,
                              void* d_out, int out_size) {
    const int*   src    = (const int*)d_in[0];
    const int*   dst    = (const int*)d_in[1];
    const float* x      = (const float*)d_in[2];
    const float* wts    = (const float*)d_in[3];
    const float* latp   = (const float*)d_in[4];
    const float* sl_w   = (const float*)d_in[5];
    const float* sl_b   = (const float*)d_in[6];
    const float* slo_w  = (const float*)d_in[7];
    const float* slo_b  = (const float*)d_in[8];
    const float* fc1_w  = (const float*)d_in[9];
    const float* w_u1   = (const float*)d_in[10];
    const float* w_v1   = (const float*)d_in[11];
    const float* w_s1   = (const float*)d_in[12];
    const float* beta1  = (const float*)d_in[13];
    const float* aw1    = (const float*)d_in[14];
    const float* theta1 = (const float*)d_in[15];
    const float* fc2_w  = (const float*)d_in[16];
    const float* w_u2   = (const float*)d_in[17];
    const float* w_v2   = (const float*)d_in[18];
    const float* w_s2   = (const float*)d_in[19];
    const float* beta2  = (const float*)d_in[20];
    const float* aw2    = (const float*)d_in[21];
    const float* theta2 = (const float*)d_in[22];
    float* out = (float*)d_out;

    int nb_scan = (NN + SB - 1) / SB;   // 49

    k_zero<<<256, 256>>>();
    k_scalars<<<1, 32>>>(beta1, aw1, theta1, beta2, aw2, theta2);
    k_latp<<<(NN + 255) / 256, 256>>>(latp, sl_w, sl_b, slo_w, slo_b);
    k_gemm1<<<(NN + BM - 1) / BM, 256>>>(x, fc1_w, w_u1, w_v1);
    k_edgeA1<<<4096, 256>>>(src, dst, w_s1);
    k_scan1<<<nb_scan, SB>>>();
    k_scan2<<<1, 64>>>(nb_scan);
    k_scan3<<<(NN + 255) / 256, 256>>>();
    k_scatter<<<(EE + 255) / 256, 256>>>(src, dst);
    k_aggrfc<<<2048, 256>>>(fc2_w, w_u2, w_v2);
    k_edgeA2<<<2048, 256>>>(src, dst, w_s2, wts);
    k_coefp2<<<1024, 256>>>();
    k_final<<<2048, 256>>>(out, out_size);
}

// round 16
// speedup vs baseline: 1.1643x; 1.0363x over previous
#include <cuda_runtime.h>
#include <math.h>

#define NN 50000
#define EE 800000
#define NF  512
#define NH  128
#define NC  16
#define EPSF 1e-9f

// ---------------- scratch (static device allocations) ----------------
__device__ float g_h1[NN * NH];
__device__ float g_hlatp[NN * NC];
__device__ float g_hlatp2[NN * NC];
__device__ float g_h2[NN * NC];
__device__ float g_el1[NN], g_er1[NN];
__device__ float g_el2[NN], g_er2[NN];
__device__ float g_indeg[NN];
__device__ float g_outw1[NN], g_inw1[NN], g_outw2[NN], g_inw2[NN];
__device__ float g_ew1[EE], g_ew2[EE];
__device__ float g_lp;
__device__ float g_scal[8];
// CSR
__device__ int g_exc[NN];
__device__ int g_bsum[64];
__device__ int g_bexc[64];
__device__ int g_start[NN];
__device__ int g_cursor[NN];
__device__ int g_csrc[EE];
__device__ int g_eid[EE];
__device__ float g_cw[EE];

// ---------------- helpers ----------------
__device__ __forceinline__ float eluf(float x) { return x > 0.f ? x : expm1f(x); }
__device__ __forceinline__ float leakyf(float x) { return x > 0.f ? x : 0.2f * x; }

__device__ __forceinline__ unsigned smem_u32(const void* p) {
    unsigned r;
    asm("{ .reg .u64 t; cvta.to.shared.u64 t, %1; cvt.u32.u64 %0, t; }"
        : "=r"(r) : "l"(p));
    return r;
}

__device__ __forceinline__ unsigned pack_bf16(float a, float b) {
    unsigned r;
    asm("cvt.rn.bf16x2.f32 %0, %1, %2;" : "=r"(r) : "f"(b), "f"(a));
    return r;
}
__device__ __forceinline__ float bf16lo_f(unsigned p) { return __uint_as_float(p << 16); }
__device__ __forceinline__ float bf16hi_f(unsigned p) { return __uint_as_float(p & 0xffff0000u); }

__device__ __forceinline__ void ldsm_x4(unsigned& r0, unsigned& r1, unsigned& r2, unsigned& r3,
                                        unsigned addr) {
    asm volatile("ldmatrix.sync.aligned.m8n8.x4.shared.b16 {%0,%1,%2,%3}, [%4];"
                 : "=r"(r0), "=r"(r1), "=r"(r2), "=r"(r3) : "r"(addr));
}
__device__ __forceinline__ void ldsm_x4_t(unsigned& r0, unsigned& r1, unsigned& r2, unsigned& r3,
                                          unsigned addr) {
    asm volatile("ldmatrix.sync.aligned.m8n8.x4.trans.shared.b16 {%0,%1,%2,%3}, [%4];"
                 : "=r"(r0), "=r"(r1), "=r"(r2), "=r"(r3) : "r"(addr));
}
__device__ __forceinline__ void mma_bf16(float* c, const unsigned* a, const unsigned* b) {
    asm volatile(
        "mma.sync.aligned.m16n8k16.row.col.f32.bf16.bf16.f32 "
        "{%0,%1,%2,%3}, {%4,%5,%6,%7}, {%8,%9}, {%0,%1,%2,%3};"
        : "+f"(c[0]), "+f"(c[1]), "+f"(c[2]), "+f"(c[3])
        : "r"(a[0]), "r"(a[1]), "r"(a[2]), "r"(a[3]), "r"(b[0]), "r"(b[1]));
}

__device__ __forceinline__ void split_pack(float v0, float v1, unsigned& hi, unsigned& lo) {
    hi = pack_bf16(v0, v1);
    float h0 = bf16lo_f(hi);
    float h1 = bf16hi_f(hi);
    lo = pack_bf16(v0 - h0, v1 - h1);
}

// ---------------- fused: zero + scalars + hlatp/hlatp2 ----------------
__global__ void k_latp(const float* __restrict__ latp,
                       const float* __restrict__ sl_w, const float* __restrict__ sl_b,
                       const float* __restrict__ slo_w, const float* __restrict__ slo_b,
                       const float* __restrict__ beta1, const float* __restrict__ aw1,
                       const float* __restrict__ theta1,
                       const float* __restrict__ beta2, const float* __restrict__ aw2,
                       const float* __restrict__ theta2) {
    __shared__ float W1[NC * NC], W2[NC * NC], B1[NC], B2[NC];
    int t = threadIdx.x;
    if (t < NC * NC) { W1[t] = sl_w[t]; W2[t] = slo_w[t]; }
    if (t < NC) { B1[t] = sl_b[t]; B2[t] = slo_b[t]; }
    __syncthreads();
    int n = blockIdx.x * blockDim.x + t;

    if (blockIdx.x == 0 && t == 0) {
        g_scal[0] = 2.f / (expf(-beta1[0]) + 1.f);
        float m1 = fmaxf(aw1[0], aw1[1]);
        float a0 = expf(aw1[0] - m1), a1 = expf(aw1[1] - m1);
        g_scal[1] = a0 / (a0 + a1);
        g_scal[2] = a1 / (a0 + a1);
        g_scal[3] = EPSF / (expf(-theta1[0]) + 1.f);
        g_scal[4] = 2.f / (expf(-beta2[0]) + 1.f);
        float m2 = fmaxf(aw2[0], aw2[1]);
        float b0 = expf(aw2[0] - m2), b1 = expf(aw2[1] - m2);
        g_scal[5] = b0 / (b0 + b1);
        g_scal[6] = b1 / (b0 + b1);
        g_scal[7] = EPSF / (expf(-theta2[0]) + 1.f);
        g_lp = 0.f;
    }
    if (n >= NN) return;

    g_indeg[n] = 0.f;
    g_outw1[n] = 0.f; g_inw1[n] = 0.f;
    g_outw2[n] = 0.f; g_inw2[n] = 0.f;
    g_el1[n] = 0.f; g_er1[n] = 0.f;

    float in[NC], t1[NC];
#pragma unroll
    for (int j = 0; j < NC; j++) in[j] = latp[n * NC + j];
#pragma unroll
    for (int c = 0; c < NC; c++) {
        float acc = B1[c];
#pragma unroll
        for (int j = 0; j < NC; j++) acc += in[j] * W1[j * NC + c];
        t1[c] = eluf(acc);
        g_hlatp[n * NC + c] = t1[c];
    }
#pragma unroll
    for (int c = 0; c < NC; c++) {
        float acc = B2[c];
#pragma unroll
        for (int j = 0; j < NC; j++) acc += t1[j] * W2[j * NC + c];
        g_hlatp2[n * NC + c] = eluf(acc);
    }
}

// ---------------- tensor GEMM: h1 = x @ fc1_w, bf16 split, double-buffered ----------------
#define BM 128
#define BN 128
#define BK 32
#define SA 40
#define SBW 136
#define ABY (BM * SA * 2)
#define BBY (BK * SBW * 2)

#define LOAD_REGS(KT) do {                                                        \
    int kbase = (KT) * BK;                                                        \
    _Pragma("unroll")                                                             \
    for (int q = 0; q < 4; q++) {                                                 \
        int gm = m0 + ar + 32 * q;                                                \
        if (gm < NN) pa[q] = *(const float4*)(x + (size_t)gm * NF + kbase + ac4); \
        else pa[q] = make_float4(0.f, 0.f, 0.f, 0.f);                             \
        int bc4 = ((tid & 7) + 8 * q) << 2;                                       \
        pb[q] = *(const float4*)(w + (size_t)(kbase + ar) * BN + bc4);            \
    }                                                                             \
} while (0)

#define STORE_STAGE(BUF) do {                                                     \
    _Pragma("unroll")                                                             \
    for (int q = 0; q < 4; q++) {                                                 \
        int r = ar + 32 * q;                                                      \
        unsigned hi, lo;                                                          \
        int ai = (r * SA + ac4) >> 1;                                             \
        split_pack(pa[q].x, pa[q].y, hi, lo);                                     \
        sAhi[BUF][ai] = hi; sAlo[BUF][ai] = lo;                                   \
        split_pack(pa[q].z, pa[q].w, hi, lo);                                     \
        sAhi[BUF][ai + 1] = hi; sAlo[BUF][ai + 1] = lo;                           \
        int bc4 = ((tid & 7) + 8 * q) << 2;                                       \
        int bi = (ar * SBW + bc4) >> 1;                                           \
        split_pack(pb[q].x, pb[q].y, hi, lo);                                     \
        sBhi[BUF][bi] = hi; sBlo[BUF][bi] = lo;                                   \
        split_pack(pb[q].z, pb[q].w, hi, lo);                                     \
        sBhi[BUF][bi + 1] = hi; sBlo[BUF][bi + 1] = lo;                           \
    }                                                                             \
} while (0)

__global__ void __launch_bounds__(256, 1)
k_gemm1(const float* __restrict__ x, const float* __restrict__ w,
        const float* __restrict__ wu, const float* __restrict__ wv) {
    __shared__ unsigned sAhi[2][BM * SA / 2];
    __shared__ unsigned sAlo[2][BM * SA / 2];
    __shared__ unsigned sBhi[2][BK * SBW / 2];
    __shared__ unsigned sBlo[2][BK * SBW / 2];

    const int tid = threadIdx.x;
    const int lane = tid & 31;
    const int wp = tid >> 5;
    const int wm = (wp & 1) * 64;
    const int wn = (wp >> 1) * 32;
    const int m0 = blockIdx.x * BM;

    const unsigned aHiB = smem_u32(sAhi);
    const unsigned aLoB = smem_u32(sAlo);
    const unsigned bHiB = smem_u32(sBhi);
    const unsigned bLoB = smem_u32(sBlo);

    const int i8 = lane >> 3;
    const int w8 = lane & 7;

    const int ar = tid >> 3;
    const int ac4 = (tid & 7) << 2;

    float acc[2][4][4];
    float acc2[2][4][4];
#pragma unroll
    for (int i = 0; i < 2; i++)
#pragma unroll
        for (int j = 0; j < 4; j++)
#pragma unroll
            for (int k = 0; k < 4; k++) { acc[i][j][k] = 0.f; acc2[i][j][k] = 0.f; }

    float4 pa[4], pb[4];
    const int NT = NF / BK;   // 16

    LOAD_REGS(0);
    STORE_STAGE(0);
    __syncthreads();

    for (int kt = 0; kt < NT; kt++) {
        const int buf = kt & 1;
        const unsigned aOff = buf ? (unsigned)ABY : 0u;
        const unsigned bOff = buf ? (unsigned)BBY : 0u;

        if (kt + 1 < NT) LOAD_REGS(kt + 1);

#pragma unroll
        for (int ks = 0; ks < 2; ks++) {
            int k0 = ks * 16;
            unsigned bh[4][2], bl[4][2];
            int brow = k0 + ((i8 & 1) << 3) + w8;
#pragma unroll
            for (int p = 0; p < 2; p++) {
                int bcol = wn + p * 16 + ((i8 >> 1) << 3);
                unsigned off = (unsigned)(brow * SBW + bcol) * 2u + bOff;
                ldsm_x4_t(bh[2 * p][0], bh[2 * p][1], bh[2 * p + 1][0], bh[2 * p + 1][1],
                          bHiB + off);
                ldsm_x4_t(bl[2 * p][0], bl[2 * p][1], bl[2 * p + 1][0], bl[2 * p + 1][1],
                          bLoB + off);
            }
#pragma unroll
            for (int mh = 0; mh < 2; mh++) {
#pragma unroll
                for (int mt = 0; mt < 2; mt++) {
                    int arow = wm + (mh * 2 + mt) * 16 + ((i8 & 1) << 3) + w8;
                    int acol = k0 + ((i8 >> 1) << 3);
                    unsigned off = (unsigned)(arow * SA + acol) * 2u + aOff;
                    unsigned ah[4], al[4];
                    ldsm_x4(ah[0], ah[1], ah[2], ah[3], aHiB + off);
                    ldsm_x4(al[0], al[1], al[2], al[3], aLoB + off);
                    float* accp0;
#pragma unroll
                    for (int nt = 0; nt < 4; nt++) {
                        accp0 = mh ? acc2[mt][nt] : acc[mt][nt];
                        mma_bf16(accp0, ah, bh[nt]);
                        mma_bf16(accp0, ah, bl[nt]);
                        mma_bf16(accp0, al, bh[nt]);
                    }
                }
            }
        }

        if (kt + 1 < NT) {
            STORE_STAGE(buf ^ 1);
            __syncthreads();
        }
    }

    // epilogue: store h1 + fused el1/er1 partials
#pragma unroll
    for (int mh = 0; mh < 2; mh++) {
#pragma unroll
        for (int mt = 0; mt < 2; mt++) {
            int r0 = m0 + wm + (mh * 2 + mt) * 16 + (lane >> 2);
            int r1 = r0 + 8;
            float pu0 = 0.f, pv0 = 0.f, pu1 = 0.f, pv1 = 0.f;
#pragma unroll
            for (int nt = 0; nt < 4; nt++) {
                const float* ac = mh ? acc2[mt][nt] : acc[mt][nt];
                int col = wn + nt * 8 + ((lane & 3) << 1);
                float u0 = wu[col], u1 = wu[col + 1];
                float v0 = wv[col], v1 = wv[col + 1];
                float l00 = leakyf(ac[0]), l01 = leakyf(ac[1]);
                float l10 = leakyf(ac[2]), l11 = leakyf(ac[3]);
                pu0 += l00 * u0 + l01 * u1;
                pv0 += l00 * v0 + l01 * v1;
                pu1 += l10 * u0 + l11 * u1;
                pv1 += l10 * v0 + l11 * v1;
                if (r0 < NN)
                    *(float2*)&g_h1[(size_t)r0 * NH + col] = make_float2(ac[0], ac[1]);
                if (r1 < NN)
                    *(float2*)&g_h1[(size_t)r1 * NH + col] = make_float2(ac[2], ac[3]);
            }
            pu0 += __shfl_down_sync(0xffffffffu, pu0, 2, 4);
            pu0 += __shfl_down_sync(0xffffffffu, pu0, 1, 4);
            pv0 += __shfl_down_sync(0xffffffffu, pv0, 2, 4);
            pv0 += __shfl_down_sync(0xffffffffu, pv0, 1, 4);
            pu1 += __shfl_down_sync(0xffffffffu, pu1, 2, 4);
            pu1 += __shfl_down_sync(0xffffffffu, pu1, 1, 4);
            pv1 += __shfl_down_sync(0xffffffffu, pv1, 2, 4);
            pv1 += __shfl_down_sync(0xffffffffu, pv1, 1, 4);
            if ((lane & 3) == 0) {
                if (r0 < NN) { atomicAdd(&g_el1[r0], pu0); atomicAdd(&g_er1[r0], pv0); }
                if (r1 < NN) { atomicAdd(&g_el1[r1], pu1); atomicAdd(&g_er1[r1], pv1); }
            }
        }
    }
}

// ---------------- layer1 edge pass A: 16-lane groups, 2 edges in flight ----------------
__global__ void k_edgeA1(const int* __restrict__ src, const int* __restrict__ dst,
                         const float* __restrict__ ws1) {
    int gt = blockIdx.x * blockDim.x + threadIdx.x;
    int l = threadIdx.x & 15;
    int grp = gt >> 4;
    int ngr = (gridDim.x * blockDim.x) >> 4;
    float wsv = ws1[l];
    float bw = g_scal[0];
    float bw0 = bw * g_scal[1], bw1 = bw * g_scal[2];

    for (int e0 = grp; e0 < EE; e0 += 2 * ngr) {
        int e1 = e0 + ngr;
        int v1 = (e1 < EE);
        int s0 = src[e0], d0_ = dst[e0];
        int s1 = v1 ? src[e1] : 0, d1_ = v1 ? dst[e1] : 0;

        const float4* as0 = (const float4*)(g_h1 + (size_t)s0 * NH);
        const float4* ad0 = (const float4*)(g_h1 + (size_t)d0_ * NH);
        const float4* as1 = (const float4*)(g_h1 + (size_t)s1 * NH);
        const float4* ad1 = (const float4*)(g_h1 + (size_t)d1_ * NH);
        float4 A0 = as0[2 * l], A1 = as0[2 * l + 1];
        float4 B0 = ad0[2 * l], B1 = ad0[2 * l + 1];
        float4 C0 = as1[2 * l], C1 = as1[2 * l + 1];
        float4 D0 = ad1[2 * l], D1 = ad1[2 * l + 1];
        float ps0 = g_hlatp[(size_t)s0 * NC + l];
        float pd0 = g_hlatp[(size_t)d0_ * NC + l];
        float ps1 = g_hlatp[(size_t)s1 * NC + l];
        float pd1 = g_hlatp[(size_t)d1_ * NC + l];

        float x0 = A0.x - B0.x, x1 = A0.y - B0.y, x2 = A0.z - B0.z, x3 = A0.w - B0.w;
        float x4 = A1.x - B1.x, x5 = A1.y - B1.y, x6 = A1.z - B1.z, x7 = A1.w - B1.w;
        float sdf0 = x0 * x0 + x1 * x1 + x2 * x2 + x3 * x3
                   + x4 * x4 + x5 * x5 + x6 * x6 + x7 * x7;
        float y0 = C0.x - D0.x, y1 = C0.y - D0.y, y2 = C0.z - D0.z, y3 = C0.w - D0.w;
        float y4 = C1.x - D1.x, y5 = C1.y - D1.y, y6 = C1.z - D1.z, y7 = C1.w - D1.w;
        float sdf1 = y0 * y0 + y1 * y1 + y2 * y2 + y3 * y3
                   + y4 * y4 + y5 * y5 + y6 * y6 + y7 * y7;

        float df0 = ps0 - pd0, df1 = ps1 - pd1;
        float sds0 = df0 * df0, sds1 = df1 * df1;
        float st0 = ps0 * wsv * pd0, st1 = ps1 * wsv * pd1;

#pragma unroll
        for (int off = 8; off; off >>= 1) {
            sdf0 += __shfl_down_sync(0xffffffffu, sdf0, off, 16);
            sdf1 += __shfl_down_sync(0xffffffffu, sdf1, off, 16);
            sds0 += __shfl_down_sync(0xffffffffu, sds0, off, 16);
            sds1 += __shfl_down_sync(0xffffffffu, sds1, off, 16);
            st0  += __shfl_down_sync(0xffffffffu, st0, off, 16);
            st1  += __shfl_down_sync(0xffffffffu, st1, off, 16);
        }
        if (l == 0) {
            float ee0 = g_el1[s0] + g_er1[d0_] + st0;
            float ew0 = expf(ee0 - bw0 * sdf0 - bw1 * sds0) + EPSF;
            g_ew1[e0] = ew0;
            atomicAdd(&g_outw1[s0], ew0);
            atomicAdd(&g_inw1[d0_], ew0);
            atomicAdd(&g_indeg[d0_], 1.0f);
            if (v1) {
                float ee1 = g_el1[s1] + g_er1[d1_] + st1;
                float ew1v = expf(ee1 - bw0 * sdf1 - bw1 * sds1) + EPSF;
                g_ew1[e1] = ew1v;
                atomicAdd(&g_outw1[s1], ew1v);
                atomicAdd(&g_inw1[d1_], ew1v);
                atomicAdd(&g_indeg[d1_], 1.0f);
            }
        }
    }
}

// ---------------- CSR build: scan indeg -> offsets ----------------
#define SB 1024
__global__ void k_scan1() {
    __shared__ int s[SB];
    int t = threadIdx.x;
    int i = blockIdx.x * SB + t;
    int v = (i < NN) ? (int)g_indeg[i] : 0;
    s[t] = v;
    __syncthreads();
    for (int off = 1; off < SB; off <<= 1) {
        int xv = (t >= off) ? s[t - off] : 0;
        __syncthreads();
        if (t >= off) s[t] += xv;
        __syncthreads();
    }
    if (i < NN) g_exc[i] = s[t] - v;
    if (t == SB - 1) g_bsum[blockIdx.x] = s[t];
}

__global__ void k_scan2(int nb) {
    __shared__ int s[64];
    int t = threadIdx.x;
    int v = (t < nb) ? g_bsum[t] : 0;
    s[t] = v;
    __syncthreads();
    for (int off = 1; off < 64; off <<= 1) {
        int xv = (t >= off) ? s[t - off] : 0;
        __syncthreads();
        if (t >= off) s[t] += xv;
        __syncthreads();
    }
    g_bexc[t] = s[t] - v;
}

__global__ void k_scan3() {
    int i = blockIdx.x * blockDim.x + threadIdx.x;
    if (i < NN) {
        int st = g_exc[i] + g_bexc[i >> 10];
        g_start[i] = st;
        g_cursor[i] = st;
    }
}

// ---------------- scatter: csrc + layer1 weight + edge id ----------------
__global__ void k_scatter(const int* __restrict__ src, const int* __restrict__ dst) {
    int e = blockIdx.x * blockDim.x + threadIdx.x;
    if (e < EE) {
        int s = src[e];
        int p = atomicAdd(&g_cursor[dst[e]], 1);
        g_csrc[p] = s;
        g_eid[p] = e;
        g_cw[p] = rsqrtf(g_outw1[s]) * g_ew1[e];
    }
}

// ---------------- fused: layer1 CSR aggregation + combine + elu + fc2 + el2/er2 ----------------
__global__ void k_aggrfc(const float* __restrict__ w, const float* __restrict__ wu,
                         const float* __restrict__ wv) {
    __shared__ float Ws[NH * NC];
    __shared__ float Hrow[8][NH];
    int t = threadIdx.x;
    for (int j = t; j < NH * NC; j += blockDim.x) Ws[j] = w[j];
    __syncthreads();

    int lane = t & 31;
    int wid = t >> 5;
    int c = lane & 15;
    int half = lane >> 4;
    int gw = (blockIdx.x * blockDim.x + t) >> 5;
    int nw = (gridDim.x * blockDim.x) >> 5;
    float wuc = wu[c], wvc = wv[c];
    float pc = g_scal[3];

    for (int n = gw; n < NN; n += nw) {
        int st = g_start[n];
        int deg = (int)g_indeg[n];
        float invin = (deg > 0) ? rsqrtf(g_inw1[n]) : 0.f;
        float4 acc = make_float4(0.f, 0.f, 0.f, 0.f);
        int j = 0;
        for (; j + 2 <= deg; j += 2) {
            int s0 = g_csrc[st + j], s1 = g_csrc[st + j + 1];
            float w0 = g_cw[st + j], w1 = g_cw[st + j + 1];
            float4 h0 = ((const float4*)(g_h1 + (size_t)s0 * NH))[lane];
            float4 h1v = ((const float4*)(g_h1 + (size_t)s1 * NH))[lane];
            acc.x += h0.x * w0 + h1v.x * w1;
            acc.y += h0.y * w0 + h1v.y * w1;
            acc.z += h0.z * w0 + h1v.z * w1;
            acc.w += h0.w * w0 + h1v.w * w1;
        }
        if (j < deg) {
            int s0 = g_csrc[st + j];
            float w0 = g_cw[st + j];
            float4 h0 = ((const float4*)(g_h1 + (size_t)s0 * NH))[lane];
            acc.x += h0.x * w0; acc.y += h0.y * w0;
            acc.z += h0.z * w0; acc.w += h0.w * w0;
        }
        float perm = pc / ((float)deg + EPSF);
        float4 hn = ((const float4*)(g_h1 + (size_t)n * NH))[lane];
        float4 o;
        o.x = eluf(acc.x * invin + hn.x * perm);
        o.y = eluf(acc.y * invin + hn.y * perm);
        o.z = eluf(acc.z * invin + hn.z * perm);
        o.w = eluf(acc.w * invin + hn.w * perm);
        *(float4*)&Hrow[wid][lane << 2] = o;
        __syncwarp();

        float acc2 = 0.f;
        int kb = half * 64;
#pragma unroll
        for (int k = 0; k < 64; k++) acc2 += Hrow[wid][kb + k] * Ws[(kb + k) * NC + c];
        acc2 += __shfl_xor_sync(0xffffffffu, acc2, 16);
        if (half == 0) g_h2[(size_t)n * NC + c] = acc2;
        float lr = leakyf(acc2);
        float pu = lr * wuc, pv = lr * wvc;
#pragma unroll
        for (int off = 8; off; off >>= 1) {
            pu += __shfl_down_sync(0xffffffffu, pu, off, 16);
            pv += __shfl_down_sync(0xffffffffu, pv, off, 16);
        }
        if (lane == 0) { g_el2[n] = pu; g_er2[n] = pv; }
        __syncwarp();
    }
}

// ---------------- layer2 edge pass A: 2 edges in flight ----------------
__global__ void k_edgeA2(const int* __restrict__ src, const int* __restrict__ dst,
                         const float* __restrict__ ws2, const float* __restrict__ wts) {
    __shared__ float redbuf[256];
    int t = threadIdx.x;
    int c = t & 15;
    int grp = (blockIdx.x * blockDim.x + t) >> 4;
    int ngr = (gridDim.x * blockDim.x) >> 4;
    float wsv = ws2[c];
    float bw = g_scal[4], w0 = g_scal[5], w1 = g_scal[6];
    float lpacc = 0.f;

    for (int e0 = grp; e0 < EE; e0 += 2 * ngr) {
        int e1 = e0 + ngr;
        int v1 = (e1 < EE);
        int s0 = src[e0], d0_ = dst[e0];
        int s1 = v1 ? src[e1] : 0, d1_ = v1 ? dst[e1] : 0;

        float hs0 = g_h2[(size_t)s0 * NC + c], hd0 = g_h2[(size_t)d0_ * NC + c];
        float ps0 = g_hlatp2[(size_t)s0 * NC + c], pd0 = g_hlatp2[(size_t)d0_ * NC + c];
        float hs1 = g_h2[(size_t)s1 * NC + c], hd1 = g_h2[(size_t)d1_ * NC + c];
        float ps1 = g_hlatp2[(size_t)s1 * NC + c], pd1 = g_hlatp2[(size_t)d1_ * NC + c];

        float df0 = hs0 - hd0, df1 = hs1 - hd1;
        float sdf0 = df0 * df0, sdf1 = df1 * df1;
        float dp0 = ps0 - pd0, dp1 = ps1 - pd1;
        float sds0 = dp0 * dp0, sds1 = dp1 * dp1;
        float pr0 = ps0 * pd0, pr1 = ps1 * pd1;
        float st0 = pr0 * wsv, st1 = pr1 * wsv;

#pragma unroll
        for (int off = 8; off; off >>= 1) {
            sdf0 += __shfl_down_sync(0xffffffffu, sdf0, off, 16);
            sdf1 += __shfl_down_sync(0xffffffffu, sdf1, off, 16);
            sds0 += __shfl_down_sync(0xffffffffu, sds0, off, 16);
            sds1 += __shfl_down_sync(0xffffffffu, sds1, off, 16);
            st0  += __shfl_down_sync(0xffffffffu, st0, off, 16);
            st1  += __shfl_down_sync(0xffffffffu, st1, off, 16);
            pr0  += __shfl_down_sync(0xffffffffu, pr0, off, 16);
            pr1  += __shfl_down_sync(0xffffffffu, pr1, off, 16);
        }
        if (c == 0) {
            float ee0 = g_el2[s0] + g_er2[d0_] + st0;
            float ew0 = expf(ee0 - bw * (w0 * sdf0 + w1 * sds0)) + EPSF;
            g_ew2[e0] = ew0;
            atomicAdd(&g_outw2[s0], ew0);
            atomicAdd(&g_inw2[d0_], ew0);
            lpacc += wts[e0] * pr0;
            if (v1) {
                float ee1 = g_el2[s1] + g_er2[d1_] + st1;
                float ew1v = expf(ee1 - bw * (w0 * sdf1 + w1 * sds1)) + EPSF;
                g_ew2[e1] = ew1v;
                atomicAdd(&g_outw2[s1], ew1v);
                atomicAdd(&g_inw2[d1_], ew1v);
                lpacc += wts[e1] * pr1;
            }
        }
    }
    redbuf[t] = lpacc;
    __syncthreads();
    for (int s2 = 128; s2; s2 >>= 1) {
        if (t < s2) redbuf[t] += redbuf[t + s2];
        __syncthreads();
    }
    if (t == 0) atomicAdd(&g_lp, redbuf[0]);
}

// ---------------- final: layer2 CSR aggregation (coef inline) + log_softmax ----------------
__global__ void k_final(float* __restrict__ out, int out_size) {
    int t = threadIdx.x;
    int c = t & 15;
    int grp = (blockIdx.x * blockDim.x + t) >> 4;
    int ngr = (gridDim.x * blockDim.x) >> 4;
    float pc = g_scal[7];

    for (int n = grp; n < NN; n += ngr) {
        int st = g_start[n];
        int deg = (int)g_indeg[n];
        float invin = (deg > 0) ? rsqrtf(g_inw2[n]) : 0.f;
        float acc = 0.f;
        int j = 0;
        for (; j + 2 <= deg; j += 2) {
            int s0 = g_csrc[st + j], s1 = g_csrc[st + j + 1];
            int ei0 = g_eid[st + j], ei1 = g_eid[st + j + 1];
            float w0 = rsqrtf(g_outw2[s0]) * g_ew2[ei0];
            float w1 = rsqrtf(g_outw2[s1]) * g_ew2[ei1];
            acc += w0 * g_h2[(size_t)s0 * NC + c] + w1 * g_h2[(size_t)s1 * NC + c];
        }
        if (j < deg) {
            int s0 = g_csrc[st + j];
            int ei0 = g_eid[st + j];
            acc += rsqrtf(g_outw2[s0]) * g_ew2[ei0] * g_h2[(size_t)s0 * NC + c];
        }
        float perm = pc / ((float)deg + EPSF);
        float v = acc * invin + g_h2[(size_t)n * NC + c] * perm;
        float xv = eluf(v);
        float m = xv;
#pragma unroll
        for (int off = 8; off; off >>= 1)
            m = fmaxf(m, __shfl_xor_sync(0xffffffffu, m, off, 16));
        float ex = expf(xv - m);
        float ssum = ex;
#pragma unroll
        for (int off = 8; off; off >>= 1)
            ssum += __shfl_xor_sync(0xffffffffu, ssum, off, 16);
        out[(size_t)n * NC + c] = xv - m - logf(ssum);
    }
    if (blockIdx.x == 0 && t == 0 && out_size > NN * NC)
        out[NN * NC] = g_lp;
}

// ---------------- launch ----------------
extern "C" void kernel_launch(void* const* d_in, const int* in_sizes, int n_in,
                              void* d_out, int out_size) {
    const int*   src    = (const int*)d_in[0];
    const int*   dst    = (const int*)d_in[1];
    const float* x      = (const float*)d_in[2];
    const float* wts    = (const float*)d_in[3];
    const float* latp   = (const float*)d_in[4];
    const float* sl_w   = (const float*)d_in[5];
    const float* sl_b   = (const float*)d_in[6];
    const float* slo_w  = (const float*)d_in[7];
    const float* slo_b  = (const float*)d_in[8];
    const float* fc1_w  = (const float*)d_in[9];
    const float* w_u1   = (const float*)d_in[10];
    const float* w_v1   = (const float*)d_in[11];
    const float* w_s1   = (const float*)d_in[12];
    const float* beta1  = (const float*)d_in[13];
    const float* aw1    = (const float*)d_in[14];
    const float* theta1 = (const float*)d_in[15];
    const float* fc2_w  = (const float*)d_in[16];
    const float* w_u2   = (const float*)d_in[17];
    const float* w_v2   = (const float*)d_in[18];
    const float* w_s2   = (const float*)d_in[19];
    const float* beta2  = (const float*)d_in[20];
    const float* aw2    = (const float*)d_in[21];
    const float* theta2 = (const float*)d_in[22];
    float* out = (float*)d_out;

    int nb_scan = (NN + SB - 1) / SB;   // 49

    k_latp<<<(NN + 255) / 256, 256>>>(latp, sl_w, sl_b, slo_w, slo_b,
                                      beta1, aw1, theta1, beta2, aw2, theta2);
    k_gemm1<<<(NN + BM - 1) / BM, 256>>>(x, fc1_w, w_u1, w_v1);
    k_edgeA1<<<4096, 256>>>(src, dst, w_s1);
    k_scan1<<<nb_scan, SB>>>();
    k_scan2<<<1, 64>>>(nb_scan);
    k_scan3<<<(NN + 255) / 256, 256>>>();
    k_scatter<<<(EE + 255) / 256, 256>>>(src, dst);
    k_aggrfc<<<2048, 256>>>(fc2_w, w_u2, w_v2);
    k_edgeA2<<<2048, 256>>>(src, dst, w_s2, wts);
    k_final<<<2048, 256>>>(out, out_size);
}